// round 1
// baseline (speedup 1.0000x reference)
#include <cuda_runtime.h>
#include <math.h>

#define Bb 8
#define Ss 512
#define Hh 768
#define Ll 12
#define NHh 12
#define HDd 64
#define FFf 3072
#define NCc 6
#define MM (Bb*Ss)          // 4096 rows

// ---------------- scratch (device globals; no allocs allowed) ----------------
__device__ float g_x[MM*Hh];
__device__ float g_q[MM*Hh];
__device__ float g_k[MM*Hh];
__device__ float g_v[MM*Hh];
__device__ float g_ctx[MM*Hh];
__device__ float g_t[MM*Hh];
__device__ float g_ff[MM*FFf];
__device__ float g_tab[129*HDd];
__device__ float g_avg[Bb*Hh];
__device__ float g_pool[Bb*Hh];

// ---------------- relative-position sinusoid table [129,64] ----------------
__global__ void tab_init_kernel(float* tab) {
    for (int idx = threadIdx.x; idx < 129*HDd; idx += blockDim.x) {
        int pos = idx / HDd;
        int i   = idx % HDd;
        double expo = (double)(2*(i/2)) / 64.0;
        double ang  = (double)pos * pow(10000.0, -expo);
        tab[idx] = (i % 2 == 0) ? (float)sin(ang) : (float)cos(ang);
    }
}

// ---------------- embedding + LayerNorm ----------------
__global__ __launch_bounds__(256) void embed_ln_kernel(
    const int* __restrict__ ids, const float* __restrict__ we,
    const float* __restrict__ pe, const float* __restrict__ te,
    const float* __restrict__ g, const float* __restrict__ bt,
    float* __restrict__ out)
{
    int r = blockIdx.x;            // 0..4095
    int s = r % Ss;
    int id = ids[r];
    int tid = threadIdx.x;
    __shared__ float red[8];
    float v[3];
    #pragma unroll
    for (int j = 0; j < 3; j++) {
        int c = tid + j*256;
        v[j] = we[(size_t)id*Hh + c] + pe[(size_t)s*Hh + c] + te[c];
    }
    // mean
    float sm = v[0] + v[1] + v[2];
    for (int o = 16; o > 0; o >>= 1) sm += __shfl_xor_sync(0xffffffff, sm, o);
    if ((tid & 31) == 0) red[tid >> 5] = sm;
    __syncthreads();
    if (tid < 8) {
        float t = red[tid];
        for (int o = 4; o > 0; o >>= 1) t += __shfl_xor_sync(0xff, t, o);
        if (tid == 0) red[0] = t;
    }
    __syncthreads();
    float mu = red[0] * (1.0f/768.0f);
    __syncthreads();
    float d0 = v[0]-mu, d1 = v[1]-mu, d2 = v[2]-mu;
    float s2 = d0*d0 + d1*d1 + d2*d2;
    for (int o = 16; o > 0; o >>= 1) s2 += __shfl_xor_sync(0xffffffff, s2, o);
    if ((tid & 31) == 0) red[tid >> 5] = s2;
    __syncthreads();
    if (tid < 8) {
        float t = red[tid];
        for (int o = 4; o > 0; o >>= 1) t += __shfl_xor_sync(0xff, t, o);
        if (tid == 0) red[0] = t;
    }
    __syncthreads();
    float inv = rsqrtf(red[0] * (1.0f/768.0f) + 1e-12f);
    #pragma unroll
    for (int j = 0; j < 3; j++) {
        int c = tid + j*256;
        out[(size_t)r*Hh + c] = (v[j]-mu) * inv * g[c] + bt[c];
    }
}

// ---------------- add-residual + LayerNorm ----------------
__global__ __launch_bounds__(256) void add_ln_kernel(
    const float* __restrict__ x, const float* __restrict__ y,
    const float* __restrict__ g, const float* __restrict__ bt,
    float* __restrict__ out)
{
    int r = blockIdx.x;
    int tid = threadIdx.x;
    __shared__ float red[8];
    float v[3];
    #pragma unroll
    for (int j = 0; j < 3; j++) {
        int c = tid + j*256;
        v[j] = x[(size_t)r*Hh + c] + y[(size_t)r*Hh + c];
    }
    float sm = v[0] + v[1] + v[2];
    for (int o = 16; o > 0; o >>= 1) sm += __shfl_xor_sync(0xffffffff, sm, o);
    if ((tid & 31) == 0) red[tid >> 5] = sm;
    __syncthreads();
    if (tid < 8) {
        float t = red[tid];
        for (int o = 4; o > 0; o >>= 1) t += __shfl_xor_sync(0xff, t, o);
        if (tid == 0) red[0] = t;
    }
    __syncthreads();
    float mu = red[0] * (1.0f/768.0f);
    __syncthreads();
    float d0 = v[0]-mu, d1 = v[1]-mu, d2 = v[2]-mu;
    float s2 = d0*d0 + d1*d1 + d2*d2;
    for (int o = 16; o > 0; o >>= 1) s2 += __shfl_xor_sync(0xffffffff, s2, o);
    if ((tid & 31) == 0) red[tid >> 5] = s2;
    __syncthreads();
    if (tid < 8) {
        float t = red[tid];
        for (int o = 4; o > 0; o >>= 1) t += __shfl_xor_sync(0xff, t, o);
        if (tid == 0) red[0] = t;
    }
    __syncthreads();
    float inv = rsqrtf(red[0] * (1.0f/768.0f) + 1e-12f);
    #pragma unroll
    for (int j = 0; j < 3; j++) {
        int c = tid + j*256;
        out[(size_t)r*Hh + c] = (v[j]-mu) * inv * g[c] + bt[c];
    }
}

// ---------------- fp32 SGEMM: C = A[M,K] @ W[K,N] + bias (optional exact GELU) ----------------
// BM=64, BN=128, BK=16, 256 threads, 8x4 per thread. M%64==0, N%128==0, K%16==0.
#define BM 64
#define BN 128
#define BK 16
__global__ __launch_bounds__(256) void sgemm_kernel(
    const float* __restrict__ A, const float* __restrict__ W,
    const float* __restrict__ bias, float* __restrict__ C,
    int M, int N, int K, int gelu)
{
    __shared__ float As[BK][BM];
    __shared__ float Bs[BK][BN];
    int tid = threadIdx.x;
    int m0 = blockIdx.y * BM;
    int n0 = blockIdx.x * BN;
    int ty = tid >> 5;        // 0..7  (row group)
    int tx = tid & 31;        // 0..31 (col group)
    float acc[8][4];
    #pragma unroll
    for (int r = 0; r < 8; r++)
        #pragma unroll
        for (int j = 0; j < 4; j++) acc[r][j] = 0.0f;

    int arow = tid >> 2;        // 0..63
    int acol = (tid & 3) * 4;   // 0,4,8,12
    int brow = tid >> 5;        // 0..7
    int bcol = (tid & 31) * 4;  // 0..124

    for (int k0 = 0; k0 < K; k0 += BK) {
        float4 av = *(const float4*)&A[(size_t)(m0+arow)*K + k0 + acol];
        As[acol+0][arow] = av.x;
        As[acol+1][arow] = av.y;
        As[acol+2][arow] = av.z;
        As[acol+3][arow] = av.w;
        float4 b0 = *(const float4*)&W[(size_t)(k0+brow  )*N + n0 + bcol];
        float4 b1 = *(const float4*)&W[(size_t)(k0+brow+8)*N + n0 + bcol];
        *(float4*)&Bs[brow  ][bcol] = b0;
        *(float4*)&Bs[brow+8][bcol] = b1;
        __syncthreads();
        #pragma unroll
        for (int k = 0; k < BK; k++) {
            float4 a0 = *(const float4*)&As[k][ty*8];
            float4 a1 = *(const float4*)&As[k][ty*8+4];
            float4 bv = *(const float4*)&Bs[k][tx*4];
            float a[8] = {a0.x,a0.y,a0.z,a0.w,a1.x,a1.y,a1.z,a1.w};
            float bb[4] = {bv.x,bv.y,bv.z,bv.w};
            #pragma unroll
            for (int r = 0; r < 8; r++)
                #pragma unroll
                for (int j = 0; j < 4; j++)
                    acc[r][j] += a[r]*bb[j];
        }
        __syncthreads();
    }
    #pragma unroll
    for (int r = 0; r < 8; r++) {
        int row = m0 + ty*8 + r;
        float4 o;
        float* op = (float*)&o;
        #pragma unroll
        for (int j = 0; j < 4; j++) {
            int col = n0 + tx*4 + j;
            float val = acc[r][j] + bias[col];
            if (gelu) val = val * normcdff(val);   // exact gelu: x*Phi(x)
            op[j] = val;
        }
        *(float4*)&C[(size_t)row*N + n0 + tx*4] = o;
    }
}

// ---------------- attention: one block per (b,h,i) row ----------------
// scores[j] = (q_i.k_j + qrel[clip(j-i)])*scale + mask_bias[b,j]; softmax;
// ctx[d] = sum_j p_j v[j,d] + sum_c w[c] tab[c,d],  w[c] = sum_{j:dist=c} p_j
__global__ __launch_bounds__(256) void attn_kernel(
    const float* __restrict__ q, const float* __restrict__ k,
    const float* __restrict__ v, const float* __restrict__ tab,
    const int* __restrict__ mask, float* __restrict__ ctx)
{
    const int b = blockIdx.z, h = blockIdx.y, i = blockIdx.x;
    int tid = threadIdx.x, lane = tid & 31, warp = tid >> 5;

    __shared__ float qv[64];
    __shared__ float qrel[129];
    __shared__ float sc[512];
    __shared__ float wbin[129];
    __shared__ float red[8];
    __shared__ float cred[4][64];

    size_t qoff = ((size_t)(b*Ss + i))*Hh + h*HDd;
    if (tid < 64) qv[tid] = q[qoff + tid];
    if (tid < 129) wbin[tid] = 0.0f;
    __syncthreads();

    // qrel[c] = q_i . tab[c]
    for (int c = warp; c < 129; c += 8) {
        float s = tab[c*64 + lane]*qv[lane] + tab[c*64 + lane + 32]*qv[lane+32];
        for (int o = 16; o > 0; o >>= 1) s += __shfl_xor_sync(0xffffffff, s, o);
        if (lane == 0) qrel[c] = s;
    }
    __syncthreads();

    // scores
    for (int j = warp; j < Ss; j += 8) {
        const float* kp = k + ((size_t)(b*Ss + j))*Hh + h*HDd;
        float s = kp[lane]*qv[lane] + kp[lane+32]*qv[lane+32];
        for (int o = 16; o > 0; o >>= 1) s += __shfl_xor_sync(0xffffffff, s, o);
        if (lane == 0) {
            int c = j - i; c = (c < -64) ? -64 : (c > 64 ? 64 : c); c += 64;
            float mb = (1.0f - (float)mask[b*Ss + j]) * -10000.0f;
            sc[j] = (s + qrel[c]) * 0.125f + mb;
        }
    }
    __syncthreads();

    // softmax (unnormalized; scale by inv at the end)
    float m = fmaxf(sc[tid], sc[tid+256]);
    for (int o = 16; o > 0; o >>= 1) m = fmaxf(m, __shfl_xor_sync(0xffffffff, m, o));
    if (lane == 0) red[warp] = m;
    __syncthreads();
    if (tid < 8) {
        float t = red[tid];
        for (int o = 4; o > 0; o >>= 1) t = fmaxf(t, __shfl_xor_sync(0xff, t, o));
        if (tid == 0) red[0] = t;
    }
    __syncthreads();
    m = red[0];
    __syncthreads();
    float e1 = __expf(sc[tid] - m);
    float e2 = __expf(sc[tid+256] - m);
    sc[tid] = e1; sc[tid+256] = e2;
    float s = e1 + e2;
    for (int o = 16; o > 0; o >>= 1) s += __shfl_xor_sync(0xffffffff, s, o);
    if (lane == 0) red[warp] = s;
    __syncthreads();
    if (tid < 8) {
        float t = red[tid];
        for (int o = 4; o > 0; o >>= 1) t += __shfl_xor_sync(0xff, t, o);
        if (tid == 0) red[0] = t;
    }
    __syncthreads();
    float inv = 1.0f / red[0];

    // rel-value bins
    {
        int c = tid - i; c = (c < -64) ? -64 : (c > 64 ? 64 : c); c += 64;
        atomicAdd(&wbin[c], e1);
        int j2 = tid + 256;
        int c2 = j2 - i; c2 = (c2 < -64) ? -64 : (c2 > 64 ? 64 : c2); c2 += 64;
        atomicAdd(&wbin[c2], e2);
    }
    __syncthreads();

    // ctx
    int d = tid & 63, g = tid >> 6;
    float acc = 0.0f;
    for (int j = g; j < Ss; j += 4)
        acc += sc[j] * v[((size_t)(b*Ss + j))*Hh + h*HDd + d];
    cred[g][d] = acc;
    __syncthreads();
    if (g == 0) {
        float c = cred[0][d] + cred[1][d] + cred[2][d] + cred[3][d];
        for (int cc = 0; cc < 129; cc++) c += wbin[cc] * tab[cc*64 + d];
        ctx[qoff + d] = c * inv;
    }
}

// ---------------- head: avg, pooled, classifier ----------------
__global__ void avg_kernel(const float* __restrict__ x, float* __restrict__ avg) {
    int b = blockIdx.x, hcol = threadIdx.x;   // 768 threads
    float s = 0.0f;
    for (int ss = 0; ss < Ss; ss++) s += x[((size_t)(b*Ss + ss))*Hh + hcol];
    avg[b*Hh + hcol] = s * (1.0f/512.0f);
}

__global__ __launch_bounds__(128) void pool_kernel(
    const float* __restrict__ x, const float* __restrict__ pw,
    const float* __restrict__ pb, float* __restrict__ pool)
{
    int b = blockIdx.y;
    int o = blockIdx.x*128 + threadIdx.x;
    __shared__ float xb[768];
    for (int j = threadIdx.x; j < 768; j += 128) xb[j] = x[(size_t)(b*Ss)*Hh + j];
    __syncthreads();
    float s = 0.0f;
    for (int hcol = 0; hcol < 768; hcol++) s += xb[hcol]*pw[(size_t)hcol*Hh + o];
    pool[b*Hh + o] = tanhf(s + pb[o]);
}

__global__ void out_kernel(const float* __restrict__ avg, const float* __restrict__ pool,
                           const float* __restrict__ cw, const float* __restrict__ cb,
                           float* __restrict__ out)
{
    int b = blockIdx.x;
    int tid = threadIdx.x;        // 192 threads
    int c = tid >> 5, lane = tid & 31;
    if (c >= NCc) return;
    float s = 0.0f;
    for (int t = lane; t < 2*Hh; t += 32) {
        float xv = (t < Hh) ? avg[b*Hh + t] : pool[b*Hh + t - Hh];
        s += xv * cw[(size_t)t*NCc + c];
    }
    for (int o = 16; o > 0; o >>= 1) s += __shfl_xor_sync(0xffffffff, s, o);
    if (lane == 0) out[b*NCc + c] = s + cb[c];
}

// ---------------- launch ----------------
extern "C" void kernel_launch(void* const* d_in, const int* in_sizes, int n_in,
                              void* d_out, int out_size)
{
    const int*   ids   = (const int*)  d_in[0];
    const int*   mask  = (const int*)  d_in[1];
    const float* we    = (const float*)d_in[2];
    const float* pe    = (const float*)d_in[3];
    const float* te    = (const float*)d_in[4];
    const float* lng   = (const float*)d_in[5];
    const float* lnb   = (const float*)d_in[6];
    const float* Wq    = (const float*)d_in[7];
    const float* bq    = (const float*)d_in[8];
    const float* Wk    = (const float*)d_in[9];
    const float* bk    = (const float*)d_in[10];
    const float* Wv    = (const float*)d_in[11];
    const float* bv    = (const float*)d_in[12];
    const float* Wo    = (const float*)d_in[13];
    const float* bo    = (const float*)d_in[14];
    const float* ln1g  = (const float*)d_in[15];
    const float* ln1b  = (const float*)d_in[16];
    const float* W1    = (const float*)d_in[17];
    const float* b1    = (const float*)d_in[18];
    const float* W2    = (const float*)d_in[19];
    const float* b2    = (const float*)d_in[20];
    const float* ln2g  = (const float*)d_in[21];
    const float* ln2b  = (const float*)d_in[22];
    const float* pw    = (const float*)d_in[23];
    const float* pb    = (const float*)d_in[24];
    const float* cw    = (const float*)d_in[25];
    const float* cb    = (const float*)d_in[26];
    float* out = (float*)d_out;

    float *x, *q, *k, *v, *ctx, *t, *ff, *tab, *avg, *pool;
    cudaGetSymbolAddress((void**)&x,    g_x);
    cudaGetSymbolAddress((void**)&q,    g_q);
    cudaGetSymbolAddress((void**)&k,    g_k);
    cudaGetSymbolAddress((void**)&v,    g_v);
    cudaGetSymbolAddress((void**)&ctx,  g_ctx);
    cudaGetSymbolAddress((void**)&t,    g_t);
    cudaGetSymbolAddress((void**)&ff,   g_ff);
    cudaGetSymbolAddress((void**)&tab,  g_tab);
    cudaGetSymbolAddress((void**)&avg,  g_avg);
    cudaGetSymbolAddress((void**)&pool, g_pool);

    tab_init_kernel<<<1, 256>>>(tab);
    embed_ln_kernel<<<MM, 256>>>(ids, we, pe, te, lng, lnb, x);

    dim3 gH(Hh/BN, MM/BM);     // (6, 64)
    dim3 gF(FFf/BN, MM/BM);    // (24, 64)

    for (int l = 0; l < Ll; l++) {
        const float* wq = Wq + (size_t)l*Hh*Hh;
        const float* wk = Wk + (size_t)l*Hh*Hh;
        const float* wv = Wv + (size_t)l*Hh*Hh;
        const float* wo = Wo + (size_t)l*Hh*Hh;
        sgemm_kernel<<<gH, 256>>>(x, wq, bq + l*Hh, q, MM, Hh, Hh, 0);
        sgemm_kernel<<<gH, 256>>>(x, wk, bk + l*Hh, k, MM, Hh, Hh, 0);
        sgemm_kernel<<<gH, 256>>>(x, wv, bv + l*Hh, v, MM, Hh, Hh, 0);
        attn_kernel<<<dim3(Ss, NHh, Bb), 256>>>(q, k, v, tab, mask, ctx);
        sgemm_kernel<<<gH, 256>>>(ctx, wo, bo + l*Hh, t, MM, Hh, Hh, 0);
        add_ln_kernel<<<MM, 256>>>(x, t, ln1g + l*Hh, ln1b + l*Hh, x);
        sgemm_kernel<<<gF, 256>>>(x, W1 + (size_t)l*Hh*FFf, b1 + l*FFf, ff, MM, FFf, Hh, 1);
        sgemm_kernel<<<gH, 256>>>(ff, W2 + (size_t)l*FFf*Hh, b2 + l*Hh, t, MM, Hh, FFf, 0);
        add_ln_kernel<<<MM, 256>>>(x, t, ln2g + l*Hh, ln2b + l*Hh, x);
    }

    avg_kernel<<<Bb, Hh>>>(x, avg);
    pool_kernel<<<dim3(6, Bb), 128>>>(x, pw, pb, pool);
    out_kernel<<<Bb, 192>>>(avg, pool, cw, cb, out);
}

// round 2
// speedup vs baseline: 1.5279x; 1.5279x over previous
#include <cuda_runtime.h>
#include <math.h>

#define Bb 8
#define Ss 512
#define Hh 768
#define Ll 12
#define NHh 12
#define HDd 64
#define FFf 3072
#define NCc 6
#define MM (Bb*Ss)          // 4096 rows

// ---------------- scratch (device globals; no allocs allowed) ----------------
__device__ float g_x[MM*Hh];
__device__ float g_q[MM*Hh];
__device__ float g_k[MM*Hh];
__device__ float g_v[MM*Hh];
__device__ float g_ctx[MM*Hh];
__device__ float g_t[MM*Hh];
__device__ float g_ff[MM*FFf];
__device__ float g_tab[129*HDd];
__device__ float g_avg[Bb*Hh];
__device__ float g_pool[Bb*Hh];

// ---------------- relative-position sinusoid table [129,64] ----------------
__global__ void tab_init_kernel(float* tab) {
    for (int idx = threadIdx.x; idx < 129*HDd; idx += blockDim.x) {
        int pos = idx / HDd;
        int i   = idx % HDd;
        double expo = (double)(2*(i/2)) / 64.0;
        double ang  = (double)pos * pow(10000.0, -expo);
        tab[idx] = (i % 2 == 0) ? (float)sin(ang) : (float)cos(ang);
    }
}

// ---------------- embedding + LayerNorm ----------------
__global__ __launch_bounds__(256) void embed_ln_kernel(
    const int* __restrict__ ids, const float* __restrict__ we,
    const float* __restrict__ pe, const float* __restrict__ te,
    const float* __restrict__ g, const float* __restrict__ bt,
    float* __restrict__ out)
{
    int r = blockIdx.x;
    int s = r % Ss;
    int id = ids[r];
    int tid = threadIdx.x;
    __shared__ float red[8];
    float v[3];
    #pragma unroll
    for (int j = 0; j < 3; j++) {
        int c = tid + j*256;
        v[j] = we[(size_t)id*Hh + c] + pe[(size_t)s*Hh + c] + te[c];
    }
    float sm = v[0] + v[1] + v[2];
    for (int o = 16; o > 0; o >>= 1) sm += __shfl_xor_sync(0xffffffff, sm, o);
    if ((tid & 31) == 0) red[tid >> 5] = sm;
    __syncthreads();
    if (tid < 8) {
        float t = red[tid];
        for (int o = 4; o > 0; o >>= 1) t += __shfl_xor_sync(0xff, t, o);
        if (tid == 0) red[0] = t;
    }
    __syncthreads();
    float mu = red[0] * (1.0f/768.0f);
    __syncthreads();
    float d0 = v[0]-mu, d1 = v[1]-mu, d2 = v[2]-mu;
    float s2 = d0*d0 + d1*d1 + d2*d2;
    for (int o = 16; o > 0; o >>= 1) s2 += __shfl_xor_sync(0xffffffff, s2, o);
    if ((tid & 31) == 0) red[tid >> 5] = s2;
    __syncthreads();
    if (tid < 8) {
        float t = red[tid];
        for (int o = 4; o > 0; o >>= 1) t += __shfl_xor_sync(0xff, t, o);
        if (tid == 0) red[0] = t;
    }
    __syncthreads();
    float inv = rsqrtf(red[0] * (1.0f/768.0f) + 1e-12f);
    #pragma unroll
    for (int j = 0; j < 3; j++) {
        int c = tid + j*256;
        out[(size_t)r*Hh + c] = (v[j]-mu) * inv * g[c] + bt[c];
    }
}

// ---------------- add-residual + LayerNorm ----------------
__global__ __launch_bounds__(256) void add_ln_kernel(
    const float* __restrict__ x, const float* __restrict__ y,
    const float* __restrict__ g, const float* __restrict__ bt,
    float* __restrict__ out)
{
    int r = blockIdx.x;
    int tid = threadIdx.x;
    __shared__ float red[8];
    float v[3];
    #pragma unroll
    for (int j = 0; j < 3; j++) {
        int c = tid + j*256;
        v[j] = x[(size_t)r*Hh + c] + y[(size_t)r*Hh + c];
    }
    float sm = v[0] + v[1] + v[2];
    for (int o = 16; o > 0; o >>= 1) sm += __shfl_xor_sync(0xffffffff, sm, o);
    if ((tid & 31) == 0) red[tid >> 5] = sm;
    __syncthreads();
    if (tid < 8) {
        float t = red[tid];
        for (int o = 4; o > 0; o >>= 1) t += __shfl_xor_sync(0xff, t, o);
        if (tid == 0) red[0] = t;
    }
    __syncthreads();
    float mu = red[0] * (1.0f/768.0f);
    __syncthreads();
    float d0 = v[0]-mu, d1 = v[1]-mu, d2 = v[2]-mu;
    float s2 = d0*d0 + d1*d1 + d2*d2;
    for (int o = 16; o > 0; o >>= 1) s2 += __shfl_xor_sync(0xffffffff, s2, o);
    if ((tid & 31) == 0) red[tid >> 5] = s2;
    __syncthreads();
    if (tid < 8) {
        float t = red[tid];
        for (int o = 4; o > 0; o >>= 1) t += __shfl_xor_sync(0xff, t, o);
        if (tid == 0) red[0] = t;
    }
    __syncthreads();
    float inv = rsqrtf(red[0] * (1.0f/768.0f) + 1e-12f);
    #pragma unroll
    for (int j = 0; j < 3; j++) {
        int c = tid + j*256;
        out[(size_t)r*Hh + c] = (v[j]-mu) * inv * g[c] + bt[c];
    }
}

// ================= fp32 SGEMM core: 128x128x16 double-buffered, 8x8/thread =================
__device__ __forceinline__ void gemm_body(
    const float* __restrict__ A, const float* __restrict__ W,
    const float* __restrict__ bias, float* __restrict__ C,
    int N, int K, int act, int m0, int n0,
    float As[2][16][132], float Bs[2][16][128])
{
    int tid = threadIdx.x;
    int tx = tid & 15, ty = tid >> 4;

    int am = tid >> 2;           // 0..63
    int ak = (tid & 3) * 4;      // 0,4,8,12
    int bk = tid >> 5;           // 0..7
    int bn = (tid & 31) * 4;

    const float* Ap0 = A + (size_t)(m0 + am) * K + ak;
    const float* Ap1 = A + (size_t)(m0 + am + 64) * K + ak;
    const float* Bp0 = W + (size_t)bk * N + n0 + bn;
    const float* Bp1 = W + (size_t)(bk + 8) * N + n0 + bn;

    float4 a0 = *(const float4*)Ap0;
    float4 a1 = *(const float4*)Ap1;
    float4 b0 = *(const float4*)Bp0;
    float4 b1 = *(const float4*)Bp1;

    float acc[8][8];
    #pragma unroll
    for (int r = 0; r < 8; r++)
        #pragma unroll
        for (int c = 0; c < 8; c++) acc[r][c] = 0.0f;

    int nt = K / 16;
    int buf = 0;
    #pragma unroll
    for (int w = 0; w < 4; w++) {
        As[0][ak+w][am]    = (&a0.x)[w];
        As[0][ak+w][am+64] = (&a1.x)[w];
    }
    *(float4*)&Bs[0][bk][bn]   = b0;
    *(float4*)&Bs[0][bk+8][bn] = b1;
    __syncthreads();

    for (int t = 0; t < nt; t++) {
        if (t + 1 < nt) {
            a0 = *(const float4*)(Ap0 + (t+1)*16);
            a1 = *(const float4*)(Ap1 + (t+1)*16);
            b0 = *(const float4*)(Bp0 + (size_t)(t+1)*16*N);
            b1 = *(const float4*)(Bp1 + (size_t)(t+1)*16*N);
        }
        #pragma unroll
        for (int kk = 0; kk < 16; kk++) {
            float4 av0 = *(float4*)&As[buf][kk][4*ty];
            float4 av1 = *(float4*)&As[buf][kk][64 + 4*ty];
            float4 bv0 = *(float4*)&Bs[buf][kk][4*tx];
            float4 bv1 = *(float4*)&Bs[buf][kk][64 + 4*tx];
            float am8[8] = {av0.x,av0.y,av0.z,av0.w,av1.x,av1.y,av1.z,av1.w};
            float bn8[8] = {bv0.x,bv0.y,bv0.z,bv0.w,bv1.x,bv1.y,bv1.z,bv1.w};
            #pragma unroll
            for (int r = 0; r < 8; r++)
                #pragma unroll
                for (int c = 0; c < 8; c++)
                    acc[r][c] += am8[r] * bn8[c];
        }
        if (t + 1 < nt) {
            buf ^= 1;
            #pragma unroll
            for (int w = 0; w < 4; w++) {
                As[buf][ak+w][am]    = (&a0.x)[w];
                As[buf][ak+w][am+64] = (&a1.x)[w];
            }
            *(float4*)&Bs[buf][bk][bn]   = b0;
            *(float4*)&Bs[buf][bk+8][bn] = b1;
        }
        __syncthreads();
    }

    #pragma unroll
    for (int r = 0; r < 8; r++) {
        int mrow = m0 + 4*ty + (r & 3) + ((r >= 4) ? 64 : 0);
        #pragma unroll
        for (int half = 0; half < 2; half++) {
            int col = n0 + half*64 + 4*tx;
            float4 o;
            #pragma unroll
            for (int j = 0; j < 4; j++) {
                float val = acc[r][half*4 + j] + bias[col + j];
                if (act) val = val * normcdff(val);
                (&o.x)[j] = val;
            }
            *(float4*)&C[(size_t)mrow*N + col] = o;
        }
    }
}

__global__ __launch_bounds__(256,2) void sgemm_kernel(
    const float* __restrict__ A, const float* __restrict__ W,
    const float* __restrict__ bias, float* __restrict__ C,
    int N, int K, int act)
{
    __shared__ float As[2][16][132];
    __shared__ float Bs[2][16][128];
    gemm_body(A, W, bias, C, N, K, act, blockIdx.y*128, blockIdx.x*128, As, Bs);
}

__global__ __launch_bounds__(256,2) void sgemm_qkv_kernel(
    const float* __restrict__ A,
    const float* __restrict__ Wq, const float* __restrict__ Wk, const float* __restrict__ Wv,
    const float* __restrict__ bq, const float* __restrict__ bk, const float* __restrict__ bv,
    float* __restrict__ q, float* __restrict__ k, float* __restrict__ v)
{
    __shared__ float As[2][16][132];
    __shared__ float Bs[2][16][128];
    int mat = blockIdx.x / 6;
    int bxx = blockIdx.x % 6;
    const float* W = (mat == 0) ? Wq : (mat == 1) ? Wk : Wv;
    const float* bi = (mat == 0) ? bq : (mat == 1) ? bk : bv;
    float* C = (mat == 0) ? q : (mat == 1) ? k : v;
    gemm_body(A, W, bi, C, Hh, Hh, 0, blockIdx.y*128, bxx*128, As, Bs);
}

// ================= tiled attention: block = (b, h, 64-query tile) =================
// smem words layout:
//   S[64][516]        @ 0       (33024)
//   Qs[64][64] swz    @ 33024   (4096)   transposed [d][i]
//   KV[8192]          @ 37120   (8192)   K: [d][128 j] swz; V: [128 j][64 d]
//   qw[64][129]       @ 45312   (8256)   qrel then wbin
//   mb[512]           @ 53568   (512)
//   rinv[64]          @ 54080   (64)
#define ATTN_SMEM_WORDS 54144
#define ATTN_SMEM_BYTES (ATTN_SMEM_WORDS*4)

__global__ __launch_bounds__(256) void attn_kernel(
    const float* __restrict__ q, const float* __restrict__ k,
    const float* __restrict__ v, const float* __restrict__ tab,
    const int* __restrict__ mask, float* __restrict__ ctx)
{
    extern __shared__ float sm[];
    float* S    = sm;
    float* Qs   = sm + 33024;
    float* KV   = sm + 37120;
    float* qw   = sm + 45312;
    float* mb   = sm + 53568;
    float* rinv = sm + 54080;

    const int b = blockIdx.z, h = blockIdx.y;
    const int i0 = blockIdx.x * 64;
    const int tid = threadIdx.x;
    const int tx = tid & 15, ty = tid >> 4;
    const size_t base = ((size_t)b * Ss) * Hh + h * HDd;

    // mask bias
    for (int j = tid; j < Ss; j += 256)
        mb[j] = (1.0f - (float)mask[b*Ss + j]) * -10000.0f;

    // Q tile transposed + swizzled: Qs[d*64 + ((i>>2)^(d&15))*4 + (i&3)]
    for (int t = tid; t < 64*16; t += 256) {
        int i = t >> 4, d0 = (t & 15) * 4;
        float4 qv = *(const float4*)&q[base + (size_t)(i0 + i)*Hh + d0];
        #pragma unroll
        for (int w = 0; w < 4; w++) {
            int d = d0 + w;
            Qs[d*64 + (((i>>2) ^ (d & 15)) << 2) + (i & 3)] = (&qv.x)[w];
        }
    }
    __syncthreads();

    // qrel[i][c] = q_i . tab[c]
    for (int e = tid; e < 64*129; e += 256) {
        int i = e & 63, c = e >> 6;
        int ig = i >> 2, il = i & 3;
        const float* tb = tab + c*64;
        float s = 0.0f;
        #pragma unroll 16
        for (int d = 0; d < 64; d++)
            s += Qs[d*64 + ((ig ^ (d & 15)) << 2) + il] * tb[d];
        qw[i*129 + c] = s;
    }
    __syncthreads();

    // ---- score phase: 4 tiles of 128 keys ----
    for (int jt = 0; jt < 4; jt++) {
        __syncthreads();
        // K tile transposed + swizzled: KV[d*128 + ((j>>2)^(d&31))*4 + (j&3)]
        for (int t = tid; t < 128*16; t += 256) {
            int j = t >> 4, d0 = (t & 15) * 4;
            float4 kv4 = *(const float4*)&k[base + (size_t)(jt*128 + j)*Hh + d0];
            #pragma unroll
            for (int w = 0; w < 4; w++) {
                int d = d0 + w;
                KV[d*128 + (((j>>2) ^ (d & 31)) << 2) + (j & 3)] = (&kv4.x)[w];
            }
        }
        __syncthreads();

        float acc[4][8];
        #pragma unroll
        for (int r = 0; r < 4; r++)
            #pragma unroll
            for (int c = 0; c < 8; c++) acc[r][c] = 0.0f;

        #pragma unroll 4
        for (int d = 0; d < 64; d++) {
            float4 a   = *(float4*)&Qs[d*64 + ((ty ^ (d & 15)) << 2)];
            float4 bv0 = *(float4*)&KV[d*128 + ((tx ^ (d & 31)) << 2)];
            float4 bv1 = *(float4*)&KV[d*128 + (((tx + 16) ^ (d & 31)) << 2)];
            float aa[4] = {a.x, a.y, a.z, a.w};
            float bb[8] = {bv0.x,bv0.y,bv0.z,bv0.w,bv1.x,bv1.y,bv1.z,bv1.w};
            #pragma unroll
            for (int r = 0; r < 4; r++)
                #pragma unroll
                for (int c = 0; c < 8; c++)
                    acc[r][c] += aa[r] * bb[c];
        }

        // write scores (+qrel, *scale, +mask)
        #pragma unroll
        for (int ii = 0; ii < 4; ii++) {
            int row = 4*ty + ii;
            int ia = i0 + row;
            #pragma unroll
            for (int half = 0; half < 2; half++) {
                int jb = jt*128 + half*64 + 4*tx;
                float4 o;
                #pragma unroll
                for (int jj = 0; jj < 4; jj++) {
                    int ja = jb + jj;
                    int c = ja - ia; c = (c < -64) ? -64 : (c > 64 ? 64 : c); c += 64;
                    (&o.x)[jj] = (acc[ii][half*4 + jj] + qw[row*129 + c]) * 0.125f + mb[ja];
                }
                *(float4*)&S[row*516 + jb] = o;
            }
        }
    }
    __syncthreads();

    // zero wbin (reuse qw)
    for (int t = tid; t < 64*129; t += 256) qw[t] = 0.0f;
    __syncthreads();

    // ---- softmax + wbin ----
    {
        int lane = tid & 31, wp = tid >> 5;
        for (int r = wp; r < 64; r += 8) {
            float* sr = &S[r*516];
            float mx = -1e30f;
            for (int j = lane; j < 512; j += 32) mx = fmaxf(mx, sr[j]);
            #pragma unroll
            for (int o = 16; o > 0; o >>= 1) mx = fmaxf(mx, __shfl_xor_sync(0xffffffff, mx, o));
            float sum = 0.0f;
            int ia = i0 + r;
            for (int j = lane; j < 512; j += 32) {
                float p = __expf(sr[j] - mx);
                sr[j] = p;
                sum += p;
                int c = j - ia; c = (c < -64) ? -64 : (c > 64 ? 64 : c); c += 64;
                atomicAdd(&qw[r*129 + c], p);
            }
            #pragma unroll
            for (int o = 16; o > 0; o >>= 1) sum += __shfl_xor_sync(0xffffffff, sum, o);
            if (lane == 0) rinv[r] = 1.0f / sum;
        }
    }

    // ---- ctx phase ----
    float4 acc2[4];
    #pragma unroll
    for (int ii = 0; ii < 4; ii++) acc2[ii] = make_float4(0.f,0.f,0.f,0.f);

    const float* srow0 = &S[(4*ty + 0)*516];
    const float* srow1 = &S[(4*ty + 1)*516];
    const float* srow2 = &S[(4*ty + 2)*516];
    const float* srow3 = &S[(4*ty + 3)*516];

    for (int jt = 0; jt < 4; jt++) {
        __syncthreads();
        // V tile natural [j][64]
        for (int t = tid; t < 128*16; t += 256) {
            int j = t >> 4, d0 = (t & 15) * 4;
            *(float4*)&KV[j*64 + d0] =
                *(const float4*)&v[base + (size_t)(jt*128 + j)*Hh + d0];
        }
        __syncthreads();

        #pragma unroll 4
        for (int j = 0; j < 128; j++) {
            float4 vv = *(float4*)&KV[j*64 + 4*tx];
            int J = jt*128 + j;
            float p0 = srow0[J], p1 = srow1[J], p2 = srow2[J], p3 = srow3[J];
            acc2[0].x += p0*vv.x; acc2[0].y += p0*vv.y; acc2[0].z += p0*vv.z; acc2[0].w += p0*vv.w;
            acc2[1].x += p1*vv.x; acc2[1].y += p1*vv.y; acc2[1].z += p1*vv.z; acc2[1].w += p1*vv.w;
            acc2[2].x += p2*vv.x; acc2[2].y += p2*vv.y; acc2[2].z += p2*vv.z; acc2[2].w += p2*vv.w;
            acc2[3].x += p3*vv.x; acc2[3].y += p3*vv.y; acc2[3].z += p3*vv.z; acc2[3].w += p3*vv.w;
        }
    }

    // rel-value: acc2 += wbin @ tab
    #pragma unroll 4
    for (int c = 0; c < 129; c++) {
        float4 tb = *(const float4*)&tab[c*64 + 4*tx];
        #pragma unroll
        for (int ii = 0; ii < 4; ii++) {
            float wv = qw[(4*ty + ii)*129 + c];
            acc2[ii].x += wv*tb.x; acc2[ii].y += wv*tb.y;
            acc2[ii].z += wv*tb.z; acc2[ii].w += wv*tb.w;
        }
    }

    #pragma unroll
    for (int ii = 0; ii < 4; ii++) {
        int row = 4*ty + ii;
        float inv = rinv[row];
        float4 o = make_float4(acc2[ii].x*inv, acc2[ii].y*inv, acc2[ii].z*inv, acc2[ii].w*inv);
        *(float4*)&ctx[base + (size_t)(i0 + row)*Hh + 4*tx] = o;
    }
}

// ---------------- head: avg, pooled, classifier ----------------
__global__ void avg_kernel(const float* __restrict__ x, float* __restrict__ avg) {
    int b = blockIdx.x, hcol = threadIdx.x;
    float s = 0.0f;
    for (int ss = 0; ss < Ss; ss++) s += x[((size_t)(b*Ss + ss))*Hh + hcol];
    avg[b*Hh + hcol] = s * (1.0f/512.0f);
}

__global__ __launch_bounds__(128) void pool_kernel(
    const float* __restrict__ x, const float* __restrict__ pw,
    const float* __restrict__ pb, float* __restrict__ pool)
{
    int b = blockIdx.y;
    int o = blockIdx.x*128 + threadIdx.x;
    __shared__ float xb[768];
    for (int j = threadIdx.x; j < 768; j += 128) xb[j] = x[(size_t)(b*Ss)*Hh + j];
    __syncthreads();
    float s = 0.0f;
    for (int hcol = 0; hcol < 768; hcol++) s += xb[hcol]*pw[(size_t)hcol*Hh + o];
    pool[b*Hh + o] = tanhf(s + pb[o]);
}

__global__ void out_kernel(const float* __restrict__ avg, const float* __restrict__ pool,
                           const float* __restrict__ cw, const float* __restrict__ cb,
                           float* __restrict__ out)
{
    int b = blockIdx.x;
    int tid = threadIdx.x;
    int c = tid >> 5, lane = tid & 31;
    if (c >= NCc) return;
    float s = 0.0f;
    for (int t = lane; t < 2*Hh; t += 32) {
        float xv = (t < Hh) ? avg[b*Hh + t] : pool[b*Hh + t - Hh];
        s += xv * cw[(size_t)t*NCc + c];
    }
    for (int o = 16; o > 0; o >>= 1) s += __shfl_xor_sync(0xffffffff, s, o);
    if (lane == 0) out[b*NCc + c] = s + cb[c];
}

// ---------------- launch ----------------
extern "C" void kernel_launch(void* const* d_in, const int* in_sizes, int n_in,
                              void* d_out, int out_size)
{
    const int*   ids   = (const int*)  d_in[0];
    const int*   mask  = (const int*)  d_in[1];
    const float* we    = (const float*)d_in[2];
    const float* pe    = (const float*)d_in[3];
    const float* te    = (const float*)d_in[4];
    const float* lng   = (const float*)d_in[5];
    const float* lnb   = (const float*)d_in[6];
    const float* Wq    = (const float*)d_in[7];
    const float* bq    = (const float*)d_in[8];
    const float* Wk    = (const float*)d_in[9];
    const float* bk    = (const float*)d_in[10];
    const float* Wv    = (const float*)d_in[11];
    const float* bv    = (const float*)d_in[12];
    const float* Wo    = (const float*)d_in[13];
    const float* bo    = (const float*)d_in[14];
    const float* ln1g  = (const float*)d_in[15];
    const float* ln1b  = (const float*)d_in[16];
    const float* W1    = (const float*)d_in[17];
    const float* b1    = (const float*)d_in[18];
    const float* W2    = (const float*)d_in[19];
    const float* b2    = (const float*)d_in[20];
    const float* ln2g  = (const float*)d_in[21];
    const float* ln2b  = (const float*)d_in[22];
    const float* pw    = (const float*)d_in[23];
    const float* pb    = (const float*)d_in[24];
    const float* cw    = (const float*)d_in[25];
    const float* cb    = (const float*)d_in[26];
    float* out = (float*)d_out;

    float *x, *q, *k, *v, *ctx, *t, *ff, *tab, *avg, *pool;
    cudaGetSymbolAddress((void**)&x,    g_x);
    cudaGetSymbolAddress((void**)&q,    g_q);
    cudaGetSymbolAddress((void**)&k,    g_k);
    cudaGetSymbolAddress((void**)&v,    g_v);
    cudaGetSymbolAddress((void**)&ctx,  g_ctx);
    cudaGetSymbolAddress((void**)&t,    g_t);
    cudaGetSymbolAddress((void**)&ff,   g_ff);
    cudaGetSymbolAddress((void**)&tab,  g_tab);
    cudaGetSymbolAddress((void**)&avg,  g_avg);
    cudaGetSymbolAddress((void**)&pool, g_pool);

    cudaFuncSetAttribute(attn_kernel, cudaFuncAttributeMaxDynamicSharedMemorySize,
                         ATTN_SMEM_BYTES);

    tab_init_kernel<<<1, 256>>>(tab);
    embed_ln_kernel<<<MM, 256>>>(ids, we, pe, te, lng, lnb, x);

    dim3 gH(Hh/128, MM/128);     // (6, 32)
    dim3 gF(FFf/128, MM/128);    // (24, 32)
    dim3 gQKV(18, MM/128);       // fused q,k,v

    for (int l = 0; l < Ll; l++) {
        sgemm_qkv_kernel<<<gQKV, 256>>>(x,
            Wq + (size_t)l*Hh*Hh, Wk + (size_t)l*Hh*Hh, Wv + (size_t)l*Hh*Hh,
            bq + l*Hh, bk + l*Hh, bv + l*Hh, q, k, v);
        attn_kernel<<<dim3(Ss/64, NHh, Bb), 256, ATTN_SMEM_BYTES>>>(q, k, v, tab, mask, ctx);
        sgemm_kernel<<<gH, 256>>>(ctx, Wo + (size_t)l*Hh*Hh, bo + l*Hh, t, Hh, Hh, 0);
        add_ln_kernel<<<MM, 256>>>(x, t, ln1g + l*Hh, ln1b + l*Hh, x);
        sgemm_kernel<<<gF, 256>>>(x, W1 + (size_t)l*Hh*FFf, b1 + l*FFf, ff, FFf, Hh, 1);
        sgemm_kernel<<<gH, 256>>>(ff, W2 + (size_t)l*FFf*Hh, b2 + l*Hh, t, Hh, FFf, 0);
        add_ln_kernel<<<MM, 256>>>(x, t, ln2g + l*Hh, ln2b + l*Hh, x);
    }

    avg_kernel<<<Bb, Hh>>>(x, avg);
    pool_kernel<<<dim3(6, Bb), 128>>>(x, pw, pb, pool);
    out_kernel<<<Bb, 192>>>(avg, pool, cw, cb, out);
}

// round 3
// speedup vs baseline: 3.3412x; 2.1867x over previous
#include <cuda_runtime.h>
#include <math.h>
#include <stdint.h>

#define Bb 8
#define Ss 512
#define Hh 768
#define Ll 12
#define NHh 12
#define HDd 64
#define FFf 3072
#define NCc 6
#define MM (Bb*Ss)          // 4096 rows
#define BHn (Bb*NHh)        // 96

// ---------------- scratch (device globals; no allocs allowed) ----------------
__device__ float g_x[MM*Hh];
__device__ float g_q[MM*Hh];
__device__ float g_k[MM*Hh];
__device__ float g_v[MM*Hh];
__device__ float g_ctx[MM*Hh];
__device__ float g_t[MM*Hh];
__device__ float g_ff[MM*FFf];
__device__ float g_tab[129*HDd];
__device__ float g_avg[Bb*Hh];
__device__ float g_pool[Bb*Hh];
__device__ float g_S[(size_t)BHn*Ss*Ss];       // 100.7 MB attention scores/probs
__device__ float g_qrel[(size_t)BHn*Ss*132];   // 26 MB
__device__ float g_wbin[(size_t)BHn*Ss*132];   // 26 MB

// ---------------- relative-position sinusoid table [129,64] ----------------
__global__ void tab_init_kernel(float* tab) {
    for (int idx = threadIdx.x; idx < 129*HDd; idx += blockDim.x) {
        int pos = idx / HDd;
        int i   = idx % HDd;
        double expo = (double)(2*(i/2)) / 64.0;
        double ang  = (double)pos * pow(10000.0, -expo);
        tab[idx] = (i % 2 == 0) ? (float)sin(ang) : (float)cos(ang);
    }
}

// ---------------- embedding + LayerNorm ----------------
__global__ __launch_bounds__(256) void embed_ln_kernel(
    const int* __restrict__ ids, const float* __restrict__ we,
    const float* __restrict__ pe, const float* __restrict__ te,
    const float* __restrict__ g, const float* __restrict__ bt,
    float* __restrict__ out)
{
    int r = blockIdx.x;
    int s = r % Ss;
    int id = ids[r];
    int tid = threadIdx.x;
    __shared__ float red[8];
    float v[3];
    #pragma unroll
    for (int j = 0; j < 3; j++) {
        int c = tid + j*256;
        v[j] = we[(size_t)id*Hh + c] + pe[(size_t)s*Hh + c] + te[c];
    }
    float sm = v[0] + v[1] + v[2];
    for (int o = 16; o > 0; o >>= 1) sm += __shfl_xor_sync(0xffffffff, sm, o);
    if ((tid & 31) == 0) red[tid >> 5] = sm;
    __syncthreads();
    if (tid < 8) {
        float t = red[tid];
        for (int o = 4; o > 0; o >>= 1) t += __shfl_xor_sync(0xff, t, o);
        if (tid == 0) red[0] = t;
    }
    __syncthreads();
    float mu = red[0] * (1.0f/768.0f);
    __syncthreads();
    float d0 = v[0]-mu, d1 = v[1]-mu, d2 = v[2]-mu;
    float s2 = d0*d0 + d1*d1 + d2*d2;
    for (int o = 16; o > 0; o >>= 1) s2 += __shfl_xor_sync(0xffffffff, s2, o);
    if ((tid & 31) == 0) red[tid >> 5] = s2;
    __syncthreads();
    if (tid < 8) {
        float t = red[tid];
        for (int o = 4; o > 0; o >>= 1) t += __shfl_xor_sync(0xff, t, o);
        if (tid == 0) red[0] = t;
    }
    __syncthreads();
    float inv = rsqrtf(red[0] * (1.0f/768.0f) + 1e-12f);
    #pragma unroll
    for (int j = 0; j < 3; j++) {
        int c = tid + j*256;
        out[(size_t)r*Hh + c] = (v[j]-mu) * inv * g[c] + bt[c];
    }
}

// ---------------- add-residual + LayerNorm ----------------
__global__ __launch_bounds__(256) void add_ln_kernel(
    const float* __restrict__ x, const float* __restrict__ y,
    const float* __restrict__ g, const float* __restrict__ bt,
    float* __restrict__ out)
{
    int r = blockIdx.x;
    int tid = threadIdx.x;
    __shared__ float red[8];
    float v[3];
    #pragma unroll
    for (int j = 0; j < 3; j++) {
        int c = tid + j*256;
        v[j] = x[(size_t)r*Hh + c] + y[(size_t)r*Hh + c];
    }
    float sm = v[0] + v[1] + v[2];
    for (int o = 16; o > 0; o >>= 1) sm += __shfl_xor_sync(0xffffffff, sm, o);
    if ((tid & 31) == 0) red[tid >> 5] = sm;
    __syncthreads();
    if (tid < 8) {
        float t = red[tid];
        for (int o = 4; o > 0; o >>= 1) t += __shfl_xor_sync(0xff, t, o);
        if (tid == 0) red[0] = t;
    }
    __syncthreads();
    float mu = red[0] * (1.0f/768.0f);
    __syncthreads();
    float d0 = v[0]-mu, d1 = v[1]-mu, d2 = v[2]-mu;
    float s2 = d0*d0 + d1*d1 + d2*d2;
    for (int o = 16; o > 0; o >>= 1) s2 += __shfl_xor_sync(0xffffffff, s2, o);
    if ((tid & 31) == 0) red[tid >> 5] = s2;
    __syncthreads();
    if (tid < 8) {
        float t = red[tid];
        for (int o = 4; o > 0; o >>= 1) t += __shfl_xor_sync(0xff, t, o);
        if (tid == 0) red[0] = t;
    }
    __syncthreads();
    float inv = rsqrtf(red[0] * (1.0f/768.0f) + 1e-12f);
    #pragma unroll
    for (int j = 0; j < 3; j++) {
        int c = tid + j*256;
        out[(size_t)r*Hh + c] = (v[j]-mu) * inv * g[c] + bt[c];
    }
}

// ================= TF32 tensor-core GEMM: 128x128x16 tiles, mma.m16n8k8 =================
__device__ __forceinline__ uint32_t cvt_tf32(float x) {
    uint32_t u;
    asm("cvt.rna.tf32.f32 %0, %1;" : "=r"(u) : "f"(x));
    return u;
}

__device__ __forceinline__ void mma_tf32(float* c, const uint32_t* a, uint32_t b0, uint32_t b1) {
    asm volatile(
        "mma.sync.aligned.m16n8k8.row.col.f32.tf32.tf32.f32 "
        "{%0,%1,%2,%3}, {%4,%5,%6,%7}, {%8,%9}, {%0,%1,%2,%3};"
        : "+f"(c[0]), "+f"(c[1]), "+f"(c[2]), "+f"(c[3])
        : "r"(a[0]), "r"(a[1]), "r"(a[2]), "r"(a[3]), "r"(b0), "r"(b1));
}

// smem word layout: As 2 x [128][20] = 5120 ; Bs 2 x [16][136] = 4352
#define AS_STRIDE 20
#define BS_STRIDE 136
#define AS_BUF 2560
#define BS_BUF 2176

__device__ __forceinline__ void tgemm_body(
    const float* __restrict__ A, const float* __restrict__ W,
    const float* __restrict__ bias, float* __restrict__ C,
    int N, int K, int act, int m0, int n0, uint32_t* sm)
{
    uint32_t* As = sm;
    uint32_t* Bs = sm + 2*AS_BUF;

    int tid = threadIdx.x;
    int lane = tid & 31, wid = tid >> 5;
    int wr = wid >> 2, wc = wid & 3;
    int g = lane >> 2, tg = lane & 3;

    float acc[4][4][4];
    #pragma unroll
    for (int mf = 0; mf < 4; mf++)
        #pragma unroll
        for (int nf = 0; nf < 4; nf++)
            #pragma unroll
            for (int i = 0; i < 4; i++) acc[mf][nf][i] = 0.0f;

    float4 pa[2], pb[2];
    #pragma unroll
    for (int j = 0; j < 2; j++) {
        int idx = tid + j*256;
        pa[j] = *(const float4*)&A[(size_t)(m0 + (idx>>2))*K + ((idx&3)<<2)];
        pb[j] = *(const float4*)&W[(size_t)(idx>>5)*N + n0 + ((idx&31)<<2)];
    }
    int buf = 0;
    #pragma unroll
    for (int j = 0; j < 2; j++) {
        int idx = tid + j*256;
        uint32_t* da = As + buf*AS_BUF + (idx>>2)*AS_STRIDE + ((idx&3)<<2);
        da[0]=cvt_tf32(pa[j].x); da[1]=cvt_tf32(pa[j].y); da[2]=cvt_tf32(pa[j].z); da[3]=cvt_tf32(pa[j].w);
        uint32_t* db = Bs + buf*BS_BUF + (idx>>5)*BS_STRIDE + ((idx&31)<<2);
        db[0]=cvt_tf32(pb[j].x); db[1]=cvt_tf32(pb[j].y); db[2]=cvt_tf32(pb[j].z); db[3]=cvt_tf32(pb[j].w);
    }
    __syncthreads();

    int nt = K >> 4;
    for (int t = 0; t < nt; t++) {
        if (t + 1 < nt) {
            int k0 = (t+1) << 4;
            #pragma unroll
            for (int j = 0; j < 2; j++) {
                int idx = tid + j*256;
                pa[j] = *(const float4*)&A[(size_t)(m0 + (idx>>2))*K + k0 + ((idx&3)<<2)];
                pb[j] = *(const float4*)&W[(size_t)(k0 + (idx>>5))*N + n0 + ((idx&31)<<2)];
            }
        }
        const uint32_t* Ab = As + buf*AS_BUF;
        const uint32_t* Bbp = Bs + buf*BS_BUF;
        #pragma unroll
        for (int k8 = 0; k8 < 2; k8++) {
            int kb = k8 * 8;
            uint32_t af[4][4];
            #pragma unroll
            for (int mf = 0; mf < 4; mf++) {
                int r = wr*64 + mf*16;
                af[mf][0] = Ab[(r+g  )*AS_STRIDE + kb+tg  ];
                af[mf][1] = Ab[(r+g+8)*AS_STRIDE + kb+tg  ];
                af[mf][2] = Ab[(r+g  )*AS_STRIDE + kb+tg+4];
                af[mf][3] = Ab[(r+g+8)*AS_STRIDE + kb+tg+4];
            }
            #pragma unroll
            for (int nf = 0; nf < 4; nf++) {
                int cn = wc*32 + nf*8 + g;
                uint32_t b0 = Bbp[(kb+tg  )*BS_STRIDE + cn];
                uint32_t b1 = Bbp[(kb+tg+4)*BS_STRIDE + cn];
                #pragma unroll
                for (int mf = 0; mf < 4; mf++)
                    mma_tf32(acc[mf][nf], af[mf], b0, b1);
            }
        }
        if (t + 1 < nt) {
            buf ^= 1;
            #pragma unroll
            for (int j = 0; j < 2; j++) {
                int idx = tid + j*256;
                uint32_t* da = As + buf*AS_BUF + (idx>>2)*AS_STRIDE + ((idx&3)<<2);
                da[0]=cvt_tf32(pa[j].x); da[1]=cvt_tf32(pa[j].y); da[2]=cvt_tf32(pa[j].z); da[3]=cvt_tf32(pa[j].w);
                uint32_t* db = Bs + buf*BS_BUF + (idx>>5)*BS_STRIDE + ((idx&31)<<2);
                db[0]=cvt_tf32(pb[j].x); db[1]=cvt_tf32(pb[j].y); db[2]=cvt_tf32(pb[j].z); db[3]=cvt_tf32(pb[j].w);
            }
        }
        __syncthreads();
    }

    #pragma unroll
    for (int mf = 0; mf < 4; mf++) {
        int r0 = m0 + wr*64 + mf*16 + g;
        #pragma unroll
        for (int nf = 0; nf < 4; nf++) {
            int c0 = n0 + wc*32 + nf*8 + tg*2;
            float bb0 = bias[c0], bb1 = bias[c0+1];
            float v00 = acc[mf][nf][0] + bb0;
            float v01 = acc[mf][nf][1] + bb1;
            float v10 = acc[mf][nf][2] + bb0;
            float v11 = acc[mf][nf][3] + bb1;
            if (act) {
                v00 = v00 * normcdff(v00);
                v01 = v01 * normcdff(v01);
                v10 = v10 * normcdff(v10);
                v11 = v11 * normcdff(v11);
            }
            float2 o0 = make_float2(v00, v01);
            float2 o1 = make_float2(v10, v11);
            *(float2*)&C[(size_t)r0*N + c0]     = o0;
            *(float2*)&C[(size_t)(r0+8)*N + c0] = o1;
        }
    }
}

__global__ __launch_bounds__(256) void tgemm_kernel(
    const float* __restrict__ A, const float* __restrict__ W,
    const float* __restrict__ bias, float* __restrict__ C,
    int N, int K, int act)
{
    __shared__ uint32_t sm[2*AS_BUF + 2*BS_BUF];
    tgemm_body(A, W, bias, C, N, K, act, blockIdx.y*128, blockIdx.x*128, sm);
}

__global__ __launch_bounds__(256) void tgemm_qkv_kernel(
    const float* __restrict__ A,
    const float* __restrict__ Wq, const float* __restrict__ Wk, const float* __restrict__ Wv,
    const float* __restrict__ bq, const float* __restrict__ bk, const float* __restrict__ bv,
    float* __restrict__ q, float* __restrict__ k, float* __restrict__ v)
{
    __shared__ uint32_t sm[2*AS_BUF + 2*BS_BUF];
    int mat = blockIdx.x / 6;
    int bxx = blockIdx.x % 6;
    const float* W = (mat == 0) ? Wq : (mat == 1) ? Wk : Wv;
    const float* bi = (mat == 0) ? bq : (mat == 1) ? bk : bv;
    float* C = (mat == 0) ? q : (mat == 1) ? k : v;
    tgemm_body(A, W, bi, C, Hh, Hh, 0, blockIdx.y*128, bxx*128, sm);
}

// ================= attention phase 1: qrel[row][c] = q_row . tab[c] =================
__global__ __launch_bounds__(256) void qrel_kernel(
    const float* __restrict__ q, const float* __restrict__ tab,
    float* __restrict__ qrel)
{
    __shared__ float Qs[64*64];
    const int b = blockIdx.z, h = blockIdx.y, i0 = blockIdx.x * 64;
    int tid = threadIdx.x;
    size_t base = ((size_t)b * Ss) * Hh + h * HDd;
    size_t rbase = ((size_t)(b*NHh + h)) * Ss + i0;

    for (int t = tid; t < 64*16; t += 256) {
        int i = t >> 4, d0 = (t & 15) * 4;
        float4 qv = *(const float4*)&q[base + (size_t)(i0 + i)*Hh + d0];
        #pragma unroll
        for (int w = 0; w < 4; w++) {
            int d = d0 + w;
            Qs[d*64 + (((i>>2) ^ (d & 15)) << 2) + (i & 3)] = (&qv.x)[w];
        }
    }
    __syncthreads();

    for (int e = tid; e < 64*129; e += 256) {
        int i = e & 63, c = e >> 6;
        int ig = i >> 2, il = i & 3;
        const float* tb = tab + c*64;
        float s = 0.0f;
        #pragma unroll 16
        for (int d = 0; d < 64; d++)
            s += Qs[d*64 + ((ig ^ (d & 15)) << 2) + il] * __ldg(&tb[d]);
        qrel[(rbase + i)*132 + c] = s;
    }
}

// ================= attention phase 2: S = (Q.K^T + qrel)*scale + mask =================
#define SC_SMEM_BYTES ((64*64 + 64*128 + 512)*4)
__global__ __launch_bounds__(256) void attn_score_kernel(
    const float* __restrict__ q, const float* __restrict__ k,
    const float* __restrict__ qrel, const int* __restrict__ mask,
    float* __restrict__ S)
{
    extern __shared__ float sm[];
    float* Qs = sm;            // 4096 words
    float* Ks = sm + 4096;     // 8192 words
    float* mb = sm + 12288;    // 512 words

    const int b = blockIdx.z, h = blockIdx.y, i0 = blockIdx.x * 64;
    int tid = threadIdx.x;
    int tx = tid & 15, ty = tid >> 4;
    size_t base = ((size_t)b * Ss) * Hh + h * HDd;
    size_t rbase = ((size_t)(b*NHh + h)) * Ss;

    for (int j = tid; j < Ss; j += 256)
        mb[j] = (1.0f - (float)mask[b*Ss + j]) * -10000.0f;

    for (int t = tid; t < 64*16; t += 256) {
        int i = t >> 4, d0 = (t & 15) * 4;
        float4 qv = *(const float4*)&q[base + (size_t)(i0 + i)*Hh + d0];
        #pragma unroll
        for (int w = 0; w < 4; w++) {
            int d = d0 + w;
            Qs[d*64 + (((i>>2) ^ (d & 15)) << 2) + (i & 3)] = (&qv.x)[w];
        }
    }

    for (int jt = 0; jt < 4; jt++) {
        __syncthreads();
        for (int t = tid; t < 128*16; t += 256) {
            int j = t >> 4, d0 = (t & 15) * 4;
            float4 kv4 = *(const float4*)&k[base + (size_t)(jt*128 + j)*Hh + d0];
            #pragma unroll
            for (int w = 0; w < 4; w++) {
                int d = d0 + w;
                Ks[d*128 + (((j>>2) ^ (d & 31)) << 2) + (j & 3)] = (&kv4.x)[w];
            }
        }
        __syncthreads();

        float acc[4][8];
        #pragma unroll
        for (int r = 0; r < 4; r++)
            #pragma unroll
            for (int c = 0; c < 8; c++) acc[r][c] = 0.0f;

        #pragma unroll 4
        for (int d = 0; d < 64; d++) {
            float4 a   = *(float4*)&Qs[d*64 + ((ty ^ (d & 15)) << 2)];
            float4 bv0 = *(float4*)&Ks[d*128 + ((tx ^ (d & 31)) << 2)];
            float4 bv1 = *(float4*)&Ks[d*128 + (((tx + 16) ^ (d & 31)) << 2)];
            float aa[4] = {a.x, a.y, a.z, a.w};
            float bb[8] = {bv0.x,bv0.y,bv0.z,bv0.w,bv1.x,bv1.y,bv1.z,bv1.w};
            #pragma unroll
            for (int r = 0; r < 4; r++)
                #pragma unroll
                for (int c = 0; c < 8; c++)
                    acc[r][c] += aa[r] * bb[c];
        }

        #pragma unroll
        for (int ii = 0; ii < 4; ii++) {
            int row = 4*ty + ii;
            int ia = i0 + row;
            size_t qroff = (rbase + ia) * 132;
            #pragma unroll
            for (int half = 0; half < 2; half++) {
                int jb = jt*128 + half*64 + 4*tx;
                float4 o;
                #pragma unroll
                for (int jj = 0; jj < 4; jj++) {
                    int ja = jb + jj;
                    int c = ja - ia; c = (c < -64) ? -64 : (c > 64 ? 64 : c); c += 64;
                    (&o.x)[jj] = (acc[ii][half*4 + jj] + __ldg(&qrel[qroff + c])) * 0.125f + mb[ja];
                }
                *(float4*)&S[(rbase + ia)*Ss + jb] = o;
            }
        }
    }
}

// ================= attention phase 3: row softmax + rel bins =================
__global__ __launch_bounds__(256) void softmax_kernel(
    float* __restrict__ S, float* __restrict__ wbin)
{
    __shared__ float wb[8][132];
    int lane = threadIdx.x & 31, wp = threadIdx.x >> 5;
    size_t rg = (size_t)blockIdx.x * 8 + wp;
    int i = (int)(rg & 511);
    float* sr = S + rg * Ss;

    for (int c = lane; c < 132; c += 32) wb[wp][c] = 0.0f;

    float4 x[4];
    #pragma unroll
    for (int qq = 0; qq < 4; qq++) x[qq] = ((float4*)sr)[lane + qq*32];

    float mx = -1e30f;
    #pragma unroll
    for (int qq = 0; qq < 4; qq++) {
        mx = fmaxf(mx, fmaxf(fmaxf(x[qq].x, x[qq].y), fmaxf(x[qq].z, x[qq].w)));
    }
    #pragma unroll
    for (int o = 16; o > 0; o >>= 1) mx = fmaxf(mx, __shfl_xor_sync(0xffffffff, mx, o));

    float sum = 0.0f;
    #pragma unroll
    for (int qq = 0; qq < 4; qq++) {
        x[qq].x = __expf(x[qq].x - mx); sum += x[qq].x;
        x[qq].y = __expf(x[qq].y - mx); sum += x[qq].y;
        x[qq].z = __expf(x[qq].z - mx); sum += x[qq].z;
        x[qq].w = __expf(x[qq].w - mx); sum += x[qq].w;
    }
    #pragma unroll
    for (int o = 16; o > 0; o >>= 1) sum += __shfl_xor_sync(0xffffffff, sum, o);
    float inv = 1.0f / sum;

    #pragma unroll
    for (int qq = 0; qq < 4; qq++) {
        x[qq].x *= inv; x[qq].y *= inv; x[qq].z *= inv; x[qq].w *= inv;
        ((float4*)sr)[lane + qq*32] = x[qq];
        int jb = (lane + qq*32) * 4;
        #pragma unroll
        for (int w = 0; w < 4; w++) {
            int j = jb + w;
            int c = j - i; c = (c < -64) ? -64 : (c > 64 ? 64 : c); c += 64;
            atomicAdd(&wb[wp][c], (&x[qq].x)[w]);
        }
    }
    __syncthreads();
    for (int c = lane; c < 132; c += 32) wbin[rg*132 + c] = wb[wp][c];
}

// ================= attention phase 4: ctx = P@V + wbin@tab =================
#define CTX_SMEM_BYTES ((64*132 + 128*68)*4)
__global__ __launch_bounds__(256) void attn_ctx_kernel(
    const float* __restrict__ S, const float* __restrict__ v,
    const float* __restrict__ wbin, const float* __restrict__ tab,
    float* __restrict__ ctx)
{
    extern __shared__ float sm[];
    float* Ps = sm;          // 64*132
    float* Vs = sm + 8448;   // 128*68

    const int b = blockIdx.z, h = blockIdx.y, i0 = blockIdx.x * 64;
    int tid = threadIdx.x;
    int tx = tid & 15, ty = tid >> 4;
    int lane = tid & 31, wp = tid >> 5;
    size_t base = ((size_t)b * Ss) * Hh + h * HDd;
    size_t rbase = ((size_t)(b*NHh + h)) * Ss;

    float4 acc2[4];
    #pragma unroll
    for (int ii = 0; ii < 4; ii++) acc2[ii] = make_float4(0.f,0.f,0.f,0.f);

    for (int jt = 0; jt < 4; jt++) {
        __syncthreads();
        for (int t = tid; t < 64*32; t += 256) {
            int row = t >> 5, c4 = t & 31;
            *(float4*)&Ps[row*132 + c4*4] =
                *(const float4*)&S[(rbase + i0 + row)*Ss + jt*128 + c4*4];
        }
        for (int t = tid; t < 128*16; t += 256) {
            int row = t >> 4, c4 = t & 15;
            *(float4*)&Vs[row*68 + c4*4] =
                *(const float4*)&v[base + (size_t)(jt*128 + row)*Hh + c4*4];
        }
        __syncthreads();

        const float* p0 = &Ps[(4*ty + 0)*132];
        const float* p1 = &Ps[(4*ty + 1)*132];
        const float* p2 = &Ps[(4*ty + 2)*132];
        const float* p3 = &Ps[(4*ty + 3)*132];
        #pragma unroll 4
        for (int j = 0; j < 128; j++) {
            float4 vv = *(float4*)&Vs[j*68 + 4*tx];
            float a0 = p0[j], a1 = p1[j], a2 = p2[j], a3 = p3[j];
            acc2[0].x += a0*vv.x; acc2[0].y += a0*vv.y; acc2[0].z += a0*vv.z; acc2[0].w += a0*vv.w;
            acc2[1].x += a1*vv.x; acc2[1].y += a1*vv.y; acc2[1].z += a1*vv.z; acc2[1].w += a1*vv.w;
            acc2[2].x += a2*vv.x; acc2[2].y += a2*vv.y; acc2[2].z += a2*vv.z; acc2[2].w += a2*vv.w;
            acc2[3].x += a3*vv.x; acc2[3].y += a3*vv.y; acc2[3].z += a3*vv.z; acc2[3].w += a3*vv.w;
        }
    }

    // rel-value: load wbin rows into Ps, then acc += wbin @ tab
    __syncthreads();
    for (int rr = wp; rr < 64; rr += 8)
        for (int c = lane; c < 132; c += 32)
            Ps[rr*132 + c] = wbin[(rbase + i0 + rr)*132 + c];
    __syncthreads();

    #pragma unroll 2
    for (int c = 0; c < 129; c++) {
        float4 tb = *(const float4*)&tab[c*64 + 4*tx];
        #pragma unroll
        for (int ii = 0; ii < 4; ii++) {
            float wv = Ps[(4*ty + ii)*132 + c];
            acc2[ii].x += wv*tb.x; acc2[ii].y += wv*tb.y;
            acc2[ii].z += wv*tb.z; acc2[ii].w += wv*tb.w;
        }
    }

    #pragma unroll
    for (int ii = 0; ii < 4; ii++)
        *(float4*)&ctx[base + (size_t)(i0 + 4*ty + ii)*Hh + 4*tx] = acc2[ii];
}

// ---------------- head: avg, pooled, classifier ----------------
__global__ void avg_kernel(const float* __restrict__ x, float* __restrict__ avg) {
    int b = blockIdx.x, hcol = threadIdx.x;
    float s = 0.0f;
    for (int ss = 0; ss < Ss; ss++) s += x[((size_t)(b*Ss + ss))*Hh + hcol];
    avg[b*Hh + hcol] = s * (1.0f/512.0f);
}

__global__ __launch_bounds__(128) void pool_kernel(
    const float* __restrict__ x, const float* __restrict__ pw,
    const float* __restrict__ pb, float* __restrict__ pool)
{
    int b = blockIdx.y;
    int o = blockIdx.x*128 + threadIdx.x;
    __shared__ float xb[768];
    for (int j = threadIdx.x; j < 768; j += 128) xb[j] = x[(size_t)(b*Ss)*Hh + j];
    __syncthreads();
    float s = 0.0f;
    for (int hcol = 0; hcol < 768; hcol++) s += xb[hcol]*pw[(size_t)hcol*Hh + o];
    pool[b*Hh + o] = tanhf(s + pb[o]);
}

__global__ void out_kernel(const float* __restrict__ avg, const float* __restrict__ pool,
                           const float* __restrict__ cw, const float* __restrict__ cb,
                           float* __restrict__ out)
{
    int b = blockIdx.x;
    int tid = threadIdx.x;
    int c = tid >> 5, lane = tid & 31;
    if (c >= NCc) return;
    float s = 0.0f;
    for (int t = lane; t < 2*Hh; t += 32) {
        float xv = (t < Hh) ? avg[b*Hh + t] : pool[b*Hh + t - Hh];
        s += xv * cw[(size_t)t*NCc + c];
    }
    for (int o = 16; o > 0; o >>= 1) s += __shfl_xor_sync(0xffffffff, s, o);
    if (lane == 0) out[b*NCc + c] = s + cb[c];
}

// ---------------- launch ----------------
extern "C" void kernel_launch(void* const* d_in, const int* in_sizes, int n_in,
                              void* d_out, int out_size)
{
    const int*   ids   = (const int*)  d_in[0];
    const int*   mask  = (const int*)  d_in[1];
    const float* we    = (const float*)d_in[2];
    const float* pe    = (const float*)d_in[3];
    const float* te    = (const float*)d_in[4];
    const float* lng   = (const float*)d_in[5];
    const float* lnb   = (const float*)d_in[6];
    const float* Wq    = (const float*)d_in[7];
    const float* bq    = (const float*)d_in[8];
    const float* Wk    = (const float*)d_in[9];
    const float* bk    = (const float*)d_in[10];
    const float* Wv    = (const float*)d_in[11];
    const float* bv    = (const float*)d_in[12];
    const float* Wo    = (const float*)d_in[13];
    const float* bo    = (const float*)d_in[14];
    const float* ln1g  = (const float*)d_in[15];
    const float* ln1b  = (const float*)d_in[16];
    const float* W1    = (const float*)d_in[17];
    const float* b1    = (const float*)d_in[18];
    const float* W2    = (const float*)d_in[19];
    const float* b2    = (const float*)d_in[20];
    const float* ln2g  = (const float*)d_in[21];
    const float* ln2b  = (const float*)d_in[22];
    const float* pw    = (const float*)d_in[23];
    const float* pb    = (const float*)d_in[24];
    const float* cw    = (const float*)d_in[25];
    const float* cb    = (const float*)d_in[26];
    float* out = (float*)d_out;

    float *x, *q, *k, *v, *ctx, *t, *ff, *tab, *avg, *pool, *S, *qrel, *wbin;
    cudaGetSymbolAddress((void**)&x,    g_x);
    cudaGetSymbolAddress((void**)&q,    g_q);
    cudaGetSymbolAddress((void**)&k,    g_k);
    cudaGetSymbolAddress((void**)&v,    g_v);
    cudaGetSymbolAddress((void**)&ctx,  g_ctx);
    cudaGetSymbolAddress((void**)&t,    g_t);
    cudaGetSymbolAddress((void**)&ff,   g_ff);
    cudaGetSymbolAddress((void**)&tab,  g_tab);
    cudaGetSymbolAddress((void**)&avg,  g_avg);
    cudaGetSymbolAddress((void**)&pool, g_pool);
    cudaGetSymbolAddress((void**)&S,    g_S);
    cudaGetSymbolAddress((void**)&qrel, g_qrel);
    cudaGetSymbolAddress((void**)&wbin, g_wbin);

    cudaFuncSetAttribute(attn_score_kernel, cudaFuncAttributeMaxDynamicSharedMemorySize, SC_SMEM_BYTES);
    cudaFuncSetAttribute(attn_ctx_kernel,   cudaFuncAttributeMaxDynamicSharedMemorySize, CTX_SMEM_BYTES);

    tab_init_kernel<<<1, 256>>>(tab);
    embed_ln_kernel<<<MM, 256>>>(ids, we, pe, te, lng, lnb, x);

    dim3 gH(Hh/128, MM/128);     // (6, 32)
    dim3 gF(FFf/128, MM/128);    // (24, 32)
    dim3 gQKV(18, MM/128);
    dim3 gA(Ss/64, NHh, Bb);     // (8, 12, 8)

    for (int l = 0; l < Ll; l++) {
        tgemm_qkv_kernel<<<gQKV, 256>>>(x,
            Wq + (size_t)l*Hh*Hh, Wk + (size_t)l*Hh*Hh, Wv + (size_t)l*Hh*Hh,
            bq + l*Hh, bk + l*Hh, bv + l*Hh, q, k, v);
        qrel_kernel<<<gA, 256>>>(q, tab, qrel);
        attn_score_kernel<<<gA, 256, SC_SMEM_BYTES>>>(q, k, qrel, mask, S);
        softmax_kernel<<<(BHn*Ss)/8, 256>>>(S, wbin);
        attn_ctx_kernel<<<gA, 256, CTX_SMEM_BYTES>>>(S, v, wbin, tab, ctx);
        tgemm_kernel<<<gH, 256>>>(ctx, Wo + (size_t)l*Hh*Hh, bo + l*Hh, t, Hh, Hh, 0);
        add_ln_kernel<<<MM, 256>>>(x, t, ln1g + l*Hh, ln1b + l*Hh, x);
        tgemm_kernel<<<gF, 256>>>(x, W1 + (size_t)l*Hh*FFf, b1 + l*FFf, ff, FFf, Hh, 1);
        tgemm_kernel<<<gH, 256>>>(ff, W2 + (size_t)l*FFf*Hh, b2 + l*Hh, t, Hh, FFf, 0);
        add_ln_kernel<<<MM, 256>>>(x, t, ln2g + l*Hh, ln2b + l*Hh, x);
    }

    avg_kernel<<<Bb, Hh>>>(x, avg);
    pool_kernel<<<dim3(6, Bb), 128>>>(x, pw, pb, pool);
    out_kernel<<<Bb, 192>>>(avg, pool, cw, cb, out);
}

// round 4
// speedup vs baseline: 4.3137x; 1.2911x over previous
#include <cuda_runtime.h>
#include <math.h>
#include <stdint.h>

#define Bb 8
#define Ss 512
#define Hh 768
#define Ll 12
#define NHh 12
#define HDd 64
#define FFf 3072
#define NCc 6
#define MM (Bb*Ss)          // 4096 rows
#define BHn (Bb*NHh)        // 96

// ---------------- scratch (device globals; no allocs allowed) ----------------
__device__ float g_x[MM*Hh];
__device__ float g_q[MM*Hh];
__device__ float g_k[MM*Hh];
__device__ float g_v[MM*Hh];
__device__ float g_ctx[MM*Hh];
__device__ float g_t[MM*Hh];
__device__ float g_ff[MM*FFf];
__device__ float g_tab[129*HDd];
__device__ float g_avg[Bb*Hh];
__device__ float g_pool[Bb*Hh];
__device__ float g_S[(size_t)BHn*Ss*Ss];       // 100.7 MB attention scores/probs
__device__ float g_wbin[(size_t)BHn*Ss*132];   // 26 MB

// ---------------- relative-position sinusoid table [129,64] ----------------
__global__ void tab_init_kernel(float* tab) {
    for (int idx = threadIdx.x; idx < 129*HDd; idx += blockDim.x) {
        int pos = idx / HDd;
        int i   = idx % HDd;
        double expo = (double)(2*(i/2)) / 64.0;
        double ang  = (double)pos * pow(10000.0, -expo);
        tab[idx] = (i % 2 == 0) ? (float)sin(ang) : (float)cos(ang);
    }
}

// ---------------- embedding + LayerNorm ----------------
__global__ __launch_bounds__(256) void embed_ln_kernel(
    const int* __restrict__ ids, const float* __restrict__ we,
    const float* __restrict__ pe, const float* __restrict__ te,
    const float* __restrict__ g, const float* __restrict__ bt,
    float* __restrict__ out)
{
    int r = blockIdx.x;
    int s = r % Ss;
    int id = ids[r];
    int tid = threadIdx.x;
    __shared__ float red[8];
    float v[3];
    #pragma unroll
    for (int j = 0; j < 3; j++) {
        int c = tid + j*256;
        v[j] = we[(size_t)id*Hh + c] + pe[(size_t)s*Hh + c] + te[c];
    }
    float sm = v[0] + v[1] + v[2];
    for (int o = 16; o > 0; o >>= 1) sm += __shfl_xor_sync(0xffffffff, sm, o);
    if ((tid & 31) == 0) red[tid >> 5] = sm;
    __syncthreads();
    if (tid < 8) {
        float t = red[tid];
        for (int o = 4; o > 0; o >>= 1) t += __shfl_xor_sync(0xff, t, o);
        if (tid == 0) red[0] = t;
    }
    __syncthreads();
    float mu = red[0] * (1.0f/768.0f);
    __syncthreads();
    float d0 = v[0]-mu, d1 = v[1]-mu, d2 = v[2]-mu;
    float s2 = d0*d0 + d1*d1 + d2*d2;
    for (int o = 16; o > 0; o >>= 1) s2 += __shfl_xor_sync(0xffffffff, s2, o);
    if ((tid & 31) == 0) red[tid >> 5] = s2;
    __syncthreads();
    if (tid < 8) {
        float t = red[tid];
        for (int o = 4; o > 0; o >>= 1) t += __shfl_xor_sync(0xff, t, o);
        if (tid == 0) red[0] = t;
    }
    __syncthreads();
    float inv = rsqrtf(red[0] * (1.0f/768.0f) + 1e-12f);
    #pragma unroll
    for (int j = 0; j < 3; j++) {
        int c = tid + j*256;
        out[(size_t)r*Hh + c] = (v[j]-mu) * inv * g[c] + bt[c];
    }
}

// ---------------- add-residual + LayerNorm ----------------
__global__ __launch_bounds__(256) void add_ln_kernel(
    const float* __restrict__ x, const float* __restrict__ y,
    const float* __restrict__ g, const float* __restrict__ bt,
    float* __restrict__ out)
{
    int r = blockIdx.x;
    int tid = threadIdx.x;
    __shared__ float red[8];
    float v[3];
    #pragma unroll
    for (int j = 0; j < 3; j++) {
        int c = tid + j*256;
        v[j] = x[(size_t)r*Hh + c] + y[(size_t)r*Hh + c];
    }
    float sm = v[0] + v[1] + v[2];
    for (int o = 16; o > 0; o >>= 1) sm += __shfl_xor_sync(0xffffffff, sm, o);
    if ((tid & 31) == 0) red[tid >> 5] = sm;
    __syncthreads();
    if (tid < 8) {
        float t = red[tid];
        for (int o = 4; o > 0; o >>= 1) t += __shfl_xor_sync(0xff, t, o);
        if (tid == 0) red[0] = t;
    }
    __syncthreads();
    float mu = red[0] * (1.0f/768.0f);
    __syncthreads();
    float d0 = v[0]-mu, d1 = v[1]-mu, d2 = v[2]-mu;
    float s2 = d0*d0 + d1*d1 + d2*d2;
    for (int o = 16; o > 0; o >>= 1) s2 += __shfl_xor_sync(0xffffffff, s2, o);
    if ((tid & 31) == 0) red[tid >> 5] = s2;
    __syncthreads();
    if (tid < 8) {
        float t = red[tid];
        for (int o = 4; o > 0; o >>= 1) t += __shfl_xor_sync(0xff, t, o);
        if (tid == 0) red[0] = t;
    }
    __syncthreads();
    float inv = rsqrtf(red[0] * (1.0f/768.0f) + 1e-12f);
    #pragma unroll
    for (int j = 0; j < 3; j++) {
        int c = tid + j*256;
        out[(size_t)r*Hh + c] = (v[j]-mu) * inv * g[c] + bt[c];
    }
}

// ================= TF32 tensor-core GEMM: 128x128x16 tiles, mma.m16n8k8 =================
__device__ __forceinline__ uint32_t cvt_tf32(float x) {
    uint32_t u;
    asm("cvt.rna.tf32.f32 %0, %1;" : "=r"(u) : "f"(x));
    return u;
}

__device__ __forceinline__ void mma_tf32(float* c, const uint32_t* a, uint32_t b0, uint32_t b1) {
    asm volatile(
        "mma.sync.aligned.m16n8k8.row.col.f32.tf32.tf32.f32 "
        "{%0,%1,%2,%3}, {%4,%5,%6,%7}, {%8,%9}, {%0,%1,%2,%3};"
        : "+f"(c[0]), "+f"(c[1]), "+f"(c[2]), "+f"(c[3])
        : "r"(a[0]), "r"(a[1]), "r"(a[2]), "r"(a[3]), "r"(b0), "r"(b1));
}

#define AS_STRIDE 20
#define BS_STRIDE 136
#define AS_BUF 2560
#define BS_BUF 2176

__device__ __forceinline__ void tgemm_body(
    const float* __restrict__ A, const float* __restrict__ W,
    const float* __restrict__ bias, float* __restrict__ C,
    int N, int K, int act, int m0, int n0, uint32_t* sm)
{
    uint32_t* As = sm;
    uint32_t* Bs = sm + 2*AS_BUF;

    int tid = threadIdx.x;
    int lane = tid & 31, wid = tid >> 5;
    int wr = wid >> 2, wc = wid & 3;
    int g = lane >> 2, tg = lane & 3;

    float acc[4][4][4];
    #pragma unroll
    for (int mf = 0; mf < 4; mf++)
        #pragma unroll
        for (int nf = 0; nf < 4; nf++)
            #pragma unroll
            for (int i = 0; i < 4; i++) acc[mf][nf][i] = 0.0f;

    float4 pa[2], pb[2];
    #pragma unroll
    for (int j = 0; j < 2; j++) {
        int idx = tid + j*256;
        pa[j] = *(const float4*)&A[(size_t)(m0 + (idx>>2))*K + ((idx&3)<<2)];
        pb[j] = *(const float4*)&W[(size_t)(idx>>5)*N + n0 + ((idx&31)<<2)];
    }
    int buf = 0;
    #pragma unroll
    for (int j = 0; j < 2; j++) {
        int idx = tid + j*256;
        uint32_t* da = As + buf*AS_BUF + (idx>>2)*AS_STRIDE + ((idx&3)<<2);
        da[0]=cvt_tf32(pa[j].x); da[1]=cvt_tf32(pa[j].y); da[2]=cvt_tf32(pa[j].z); da[3]=cvt_tf32(pa[j].w);
        uint32_t* db = Bs + buf*BS_BUF + (idx>>5)*BS_STRIDE + ((idx&31)<<2);
        db[0]=cvt_tf32(pb[j].x); db[1]=cvt_tf32(pb[j].y); db[2]=cvt_tf32(pb[j].z); db[3]=cvt_tf32(pb[j].w);
    }
    __syncthreads();

    int nt = K >> 4;
    for (int t = 0; t < nt; t++) {
        if (t + 1 < nt) {
            int k0 = (t+1) << 4;
            #pragma unroll
            for (int j = 0; j < 2; j++) {
                int idx = tid + j*256;
                pa[j] = *(const float4*)&A[(size_t)(m0 + (idx>>2))*K + k0 + ((idx&3)<<2)];
                pb[j] = *(const float4*)&W[(size_t)(k0 + (idx>>5))*N + n0 + ((idx&31)<<2)];
            }
        }
        const uint32_t* Ab = As + buf*AS_BUF;
        const uint32_t* Bbp = Bs + buf*BS_BUF;
        #pragma unroll
        for (int k8 = 0; k8 < 2; k8++) {
            int kb = k8 * 8;
            uint32_t af[4][4];
            #pragma unroll
            for (int mf = 0; mf < 4; mf++) {
                int r = wr*64 + mf*16;
                af[mf][0] = Ab[(r+g  )*AS_STRIDE + kb+tg  ];
                af[mf][1] = Ab[(r+g+8)*AS_STRIDE + kb+tg  ];
                af[mf][2] = Ab[(r+g  )*AS_STRIDE + kb+tg+4];
                af[mf][3] = Ab[(r+g+8)*AS_STRIDE + kb+tg+4];
            }
            #pragma unroll
            for (int nf = 0; nf < 4; nf++) {
                int cn = wc*32 + nf*8 + g;
                uint32_t b0 = Bbp[(kb+tg  )*BS_STRIDE + cn];
                uint32_t b1 = Bbp[(kb+tg+4)*BS_STRIDE + cn];
                #pragma unroll
                for (int mf = 0; mf < 4; mf++)
                    mma_tf32(acc[mf][nf], af[mf], b0, b1);
            }
        }
        if (t + 1 < nt) {
            buf ^= 1;
            #pragma unroll
            for (int j = 0; j < 2; j++) {
                int idx = tid + j*256;
                uint32_t* da = As + buf*AS_BUF + (idx>>2)*AS_STRIDE + ((idx&3)<<2);
                da[0]=cvt_tf32(pa[j].x); da[1]=cvt_tf32(pa[j].y); da[2]=cvt_tf32(pa[j].z); da[3]=cvt_tf32(pa[j].w);
                uint32_t* db = Bs + buf*BS_BUF + (idx>>5)*BS_STRIDE + ((idx&31)<<2);
                db[0]=cvt_tf32(pb[j].x); db[1]=cvt_tf32(pb[j].y); db[2]=cvt_tf32(pb[j].z); db[3]=cvt_tf32(pb[j].w);
            }
        }
        __syncthreads();
    }

    #pragma unroll
    for (int mf = 0; mf < 4; mf++) {
        int r0 = m0 + wr*64 + mf*16 + g;
        #pragma unroll
        for (int nf = 0; nf < 4; nf++) {
            int c0 = n0 + wc*32 + nf*8 + tg*2;
            float bb0 = bias[c0], bb1 = bias[c0+1];
            float v00 = acc[mf][nf][0] + bb0;
            float v01 = acc[mf][nf][1] + bb1;
            float v10 = acc[mf][nf][2] + bb0;
            float v11 = acc[mf][nf][3] + bb1;
            if (act) {
                v00 = v00 * normcdff(v00);
                v01 = v01 * normcdff(v01);
                v10 = v10 * normcdff(v10);
                v11 = v11 * normcdff(v11);
            }
            float2 o0 = make_float2(v00, v01);
            float2 o1 = make_float2(v10, v11);
            *(float2*)&C[(size_t)r0*N + c0]     = o0;
            *(float2*)&C[(size_t)(r0+8)*N + c0] = o1;
        }
    }
}

__global__ __launch_bounds__(256) void tgemm_kernel(
    const float* __restrict__ A, const float* __restrict__ W,
    const float* __restrict__ bias, float* __restrict__ C,
    int N, int K, int act)
{
    __shared__ uint32_t sm[2*AS_BUF + 2*BS_BUF];
    tgemm_body(A, W, bias, C, N, K, act, blockIdx.y*128, blockIdx.x*128, sm);
}

__global__ __launch_bounds__(256) void tgemm_qkv_kernel(
    const float* __restrict__ A,
    const float* __restrict__ Wq, const float* __restrict__ Wk, const float* __restrict__ Wv,
    const float* __restrict__ bq, const float* __restrict__ bk, const float* __restrict__ bv,
    float* __restrict__ q, float* __restrict__ k, float* __restrict__ v)
{
    __shared__ uint32_t sm[2*AS_BUF + 2*BS_BUF];
    int mat = blockIdx.x / 6;
    int bxx = blockIdx.x % 6;
    const float* W = (mat == 0) ? Wq : (mat == 1) ? Wk : Wv;
    const float* bi = (mat == 0) ? bq : (mat == 1) ? bk : bv;
    float* C = (mat == 0) ? q : (mat == 1) ? k : v;
    tgemm_body(A, W, bi, C, Hh, Hh, 0, blockIdx.y*128, bxx*128, sm);
}

// ================= fused attention front-end =================
// qrel (in smem) + scores (Q.K^T + qrel)*scale + mask -> S, then in-kernel
// softmax (re-reading L2-hot S rows), normalized P -> S, wbin via gather identity.
// smem words: Qs 4096 | KT 8448 (tabT then K tiles) | qw 8448 | mb 512 = 21504 w = 86016 B
#define FUSED_SMEM_WORDS 21504
#define FUSED_SMEM_BYTES (FUSED_SMEM_WORDS*4)

__global__ __launch_bounds__(256) void attn_fused_kernel(
    const float* __restrict__ q, const float* __restrict__ k,
    const float* __restrict__ tab, const int* __restrict__ mask,
    float* S, float* __restrict__ wbin)
{
    extern __shared__ float sm[];
    float* Qs = sm;            // 4096:  [d][i swz]
    float* KT = sm + 4096;     // 8448:  tabT [d][132], later K tiles [d][128 swz]
    float* qw = sm + 12544;    // 8448:  qrel [64][132]
    float* mb = sm + 20992;    // 512

    const int b = blockIdx.z, h = blockIdx.y, i0 = blockIdx.x * 64;
    const int tid = threadIdx.x;
    const int tx = tid & 15, ty = tid >> 4;
    const size_t base = ((size_t)b * Ss) * Hh + h * HDd;
    const size_t rbase = ((size_t)(b*NHh + h)) * Ss;

    for (int j = tid; j < Ss; j += 256)
        mb[j] = (1.0f - (float)mask[b*Ss + j]) * -10000.0f;

    // Q tile transposed + swizzled
    for (int t = tid; t < 64*16; t += 256) {
        int i = t >> 4, d0 = (t & 15) * 4;
        float4 qv = *(const float4*)&q[base + (size_t)(i0 + i)*Hh + d0];
        #pragma unroll
        for (int w = 0; w < 4; w++) {
            int d = d0 + w;
            Qs[d*64 + (((i>>2) ^ (d & 15)) << 2) + (i & 3)] = (&qv.x)[w];
        }
    }
    // tab transposed into KT: tabT[d][c], c<129
    for (int t = tid; t < 129*16; t += 256) {
        int c = t >> 4, d0 = (t & 15) * 4;
        float4 tv = *(const float4*)&tab[c*64 + d0];
        #pragma unroll
        for (int w = 0; w < 4; w++)
            KT[(d0 + w)*132 + c] = (&tv.x)[w];
    }
    __syncthreads();

    // ---- qrel: qw[i][c] = q_i . tab[c], register-tiled like a score tile ----
    {
        float acc[4][8];
        #pragma unroll
        for (int r = 0; r < 4; r++)
            #pragma unroll
            for (int c = 0; c < 8; c++) acc[r][c] = 0.0f;
        #pragma unroll 4
        for (int d = 0; d < 64; d++) {
            float4 a   = *(float4*)&Qs[d*64 + ((ty ^ (d & 15)) << 2)];
            float4 bv0 = *(float4*)&KT[d*132 + 4*tx];
            float4 bv1 = *(float4*)&KT[d*132 + 64 + 4*tx];
            float aa[4] = {a.x, a.y, a.z, a.w};
            float bb[8] = {bv0.x,bv0.y,bv0.z,bv0.w,bv1.x,bv1.y,bv1.z,bv1.w};
            #pragma unroll
            for (int r = 0; r < 4; r++)
                #pragma unroll
                for (int c = 0; c < 8; c++)
                    acc[r][c] += aa[r] * bb[c];
        }
        #pragma unroll
        for (int ii = 0; ii < 4; ii++) {
            int row = 4*ty + ii;
            #pragma unroll
            for (int half = 0; half < 2; half++)
                *(float4*)&qw[row*132 + half*64 + 4*tx] =
                    make_float4(acc[ii][half*4], acc[ii][half*4+1],
                                acc[ii][half*4+2], acc[ii][half*4+3]);
        }
        // column 128: partial dots over d = 4tx..4tx+3, reduce across 16-lane group
        float p[4] = {0.f, 0.f, 0.f, 0.f};
        #pragma unroll
        for (int w = 0; w < 4; w++) {
            int d = 4*tx + w;
            float tv = KT[d*132 + 128];
            float4 a = *(float4*)&Qs[d*64 + ((ty ^ (d & 15)) << 2)];
            p[0] += a.x*tv; p[1] += a.y*tv; p[2] += a.z*tv; p[3] += a.w*tv;
        }
        #pragma unroll
        for (int o = 8; o > 0; o >>= 1) {
            #pragma unroll
            for (int ii = 0; ii < 4; ii++)
                p[ii] += __shfl_xor_sync(0xffffffff, p[ii], o);
        }
        if (tx == 0) {
            #pragma unroll
            for (int ii = 0; ii < 4; ii++)
                qw[(4*ty + ii)*132 + 128] = p[ii];
        }
    }

    // ---- score phase: 4 tiles of 128 keys (KT reused for K) ----
    for (int jt = 0; jt < 4; jt++) {
        __syncthreads();
        for (int t = tid; t < 128*16; t += 256) {
            int j = t >> 4, d0 = (t & 15) * 4;
            float4 kv4 = *(const float4*)&k[base + (size_t)(jt*128 + j)*Hh + d0];
            #pragma unroll
            for (int w = 0; w < 4; w++) {
                int d = d0 + w;
                KT[d*128 + (((j>>2) ^ (d & 31)) << 2) + (j & 3)] = (&kv4.x)[w];
            }
        }
        __syncthreads();

        float acc[4][8];
        #pragma unroll
        for (int r = 0; r < 4; r++)
            #pragma unroll
            for (int c = 0; c < 8; c++) acc[r][c] = 0.0f;

        #pragma unroll 4
        for (int d = 0; d < 64; d++) {
            float4 a   = *(float4*)&Qs[d*64 + ((ty ^ (d & 15)) << 2)];
            float4 bv0 = *(float4*)&KT[d*128 + ((tx ^ (d & 31)) << 2)];
            float4 bv1 = *(float4*)&KT[d*128 + (((tx + 16) ^ (d & 31)) << 2)];
            float aa[4] = {a.x, a.y, a.z, a.w};
            float bb[8] = {bv0.x,bv0.y,bv0.z,bv0.w,bv1.x,bv1.y,bv1.z,bv1.w};
            #pragma unroll
            for (int r = 0; r < 4; r++)
                #pragma unroll
                for (int c = 0; c < 8; c++)
                    acc[r][c] += aa[r] * bb[c];
        }

        #pragma unroll
        for (int ii = 0; ii < 4; ii++) {
            int row = 4*ty + ii;
            int ia = i0 + row;
            #pragma unroll
            for (int half = 0; half < 2; half++) {
                int jb = jt*128 + half*64 + 4*tx;
                float4 o;
                #pragma unroll
                for (int jj = 0; jj < 4; jj++) {
                    int ja = jb + jj;
                    int c = ja - ia; c = (c < -64) ? -64 : (c > 64 ? 64 : c); c += 64;
                    (&o.x)[jj] = (acc[ii][half*4 + jj] + qw[row*132 + c]) * 0.125f + mb[ja];
                }
                *(float4*)&S[(rbase + ia)*Ss + jb] = o;
            }
        }
    }
    __syncthreads();

    // ---- softmax + wbin (warp per row; S rows are L2-hot) ----
    {
        int lane = tid & 31, wp = tid >> 5;
        for (int rr = wp; rr < 64; rr += 8) {
            int i = i0 + rr;
            float* srow = S + (rbase + i)*Ss;
            float4* s4 = (float4*)srow;
            float4 x[4];
            #pragma unroll
            for (int qq = 0; qq < 4; qq++) x[qq] = s4[lane + 32*qq];

            float mx = -1e30f;
            #pragma unroll
            for (int qq = 0; qq < 4; qq++)
                mx = fmaxf(mx, fmaxf(fmaxf(x[qq].x, x[qq].y), fmaxf(x[qq].z, x[qq].w)));
            #pragma unroll
            for (int o = 16; o > 0; o >>= 1) mx = fmaxf(mx, __shfl_xor_sync(0xffffffff, mx, o));

            float sum = 0.0f;
            #pragma unroll
            for (int qq = 0; qq < 4; qq++) {
                x[qq].x = __expf(x[qq].x - mx); sum += x[qq].x;
                x[qq].y = __expf(x[qq].y - mx); sum += x[qq].y;
                x[qq].z = __expf(x[qq].z - mx); sum += x[qq].z;
                x[qq].w = __expf(x[qq].w - mx); sum += x[qq].w;
            }
            #pragma unroll
            for (int o = 16; o > 0; o >>= 1) sum += __shfl_xor_sync(0xffffffff, sum, o);
            float inv = 1.0f / sum;

            float* wrow = wbin + (rbase + i)*132;
            *(float4*)&wrow[lane*4] = make_float4(0.f,0.f,0.f,0.f);
            if (lane == 0) *(float4*)&wrow[128] = make_float4(0.f,0.f,0.f,0.f);
            __syncwarp();

            float lo = 0.0f, hi = 0.0f;
            #pragma unroll
            for (int qq = 0; qq < 4; qq++) {
                x[qq].x *= inv; x[qq].y *= inv; x[qq].z *= inv; x[qq].w *= inv;
                s4[lane + 32*qq] = x[qq];
                int jb = (lane + 32*qq) * 4;
                #pragma unroll
                for (int w = 0; w < 4; w++) {
                    int d = jb + w - i;
                    float pv = (&x[qq].x)[w];
                    if (d <= -64)      lo += pv;
                    else if (d >= 64)  hi += pv;
                    else               wrow[d + 64] = pv;
                }
            }
            #pragma unroll
            for (int o = 16; o > 0; o >>= 1) {
                lo += __shfl_xor_sync(0xffffffff, lo, o);
                hi += __shfl_xor_sync(0xffffffff, hi, o);
            }
            if (lane == 0) { wrow[0] = lo; wrow[128] = hi; }
        }
    }
}

// ================= attention ctx: ctx = P@V + wbin@tab =================
#define CTX_SMEM_BYTES ((64*132 + 128*68)*4)
__global__ __launch_bounds__(256) void attn_ctx_kernel(
    const float* __restrict__ S, const float* __restrict__ v,
    const float* __restrict__ wbin, const float* __restrict__ tab,
    float* __restrict__ ctx)
{
    extern __shared__ float sm[];
    float* Ps = sm;          // 64*132
    float* Vs = sm + 8448;   // 128*68

    const int b = blockIdx.z, h = blockIdx.y, i0 = blockIdx.x * 64;
    int tid = threadIdx.x;
    int tx = tid & 15, ty = tid >> 4;
    int lane = tid & 31, wp = tid >> 5;
    size_t base = ((size_t)b * Ss) * Hh + h * HDd;
    size_t rbase = ((size_t)(b*NHh + h)) * Ss;

    float4 acc2[4];
    #pragma unroll
    for (int ii = 0; ii < 4; ii++) acc2[ii] = make_float4(0.f,0.f,0.f,0.f);

    for (int jt = 0; jt < 4; jt++) {
        __syncthreads();
        for (int t = tid; t < 64*32; t += 256) {
            int row = t >> 5, c4 = t & 31;
            *(float4*)&Ps[row*132 + c4*4] =
                *(const float4*)&S[(rbase + i0 + row)*Ss + jt*128 + c4*4];
        }
        for (int t = tid; t < 128*16; t += 256) {
            int row = t >> 4, c4 = t & 15;
            *(float4*)&Vs[row*68 + c4*4] =
                *(const float4*)&v[base + (size_t)(jt*128 + row)*Hh + c4*4];
        }
        __syncthreads();

        const float* p0 = &Ps[(4*ty + 0)*132];
        const float* p1 = &Ps[(4*ty + 1)*132];
        const float* p2 = &Ps[(4*ty + 2)*132];
        const float* p3 = &Ps[(4*ty + 3)*132];
        #pragma unroll 4
        for (int j = 0; j < 128; j++) {
            float4 vv = *(float4*)&Vs[j*68 + 4*tx];
            float a0 = p0[j], a1 = p1[j], a2 = p2[j], a3 = p3[j];
            acc2[0].x += a0*vv.x; acc2[0].y += a0*vv.y; acc2[0].z += a0*vv.z; acc2[0].w += a0*vv.w;
            acc2[1].x += a1*vv.x; acc2[1].y += a1*vv.y; acc2[1].z += a1*vv.z; acc2[1].w += a1*vv.w;
            acc2[2].x += a2*vv.x; acc2[2].y += a2*vv.y; acc2[2].z += a2*vv.z; acc2[2].w += a2*vv.w;
            acc2[3].x += a3*vv.x; acc2[3].y += a3*vv.y; acc2[3].z += a3*vv.z; acc2[3].w += a3*vv.w;
        }
    }

    __syncthreads();
    for (int rr = wp; rr < 64; rr += 8)
        for (int c = lane; c < 132; c += 32)
            Ps[rr*132 + c] = wbin[(rbase + i0 + rr)*132 + c];
    __syncthreads();

    #pragma unroll 2
    for (int c = 0; c < 129; c++) {
        float4 tb = *(const float4*)&tab[c*64 + 4*tx];
        #pragma unroll
        for (int ii = 0; ii < 4; ii++) {
            float wv = Ps[(4*ty + ii)*132 + c];
            acc2[ii].x += wv*tb.x; acc2[ii].y += wv*tb.y;
            acc2[ii].z += wv*tb.z; acc2[ii].w += wv*tb.w;
        }
    }

    #pragma unroll
    for (int ii = 0; ii < 4; ii++)
        *(float4*)&ctx[base + (size_t)(i0 + 4*ty + ii)*Hh + 4*tx] = acc2[ii];
}

// ---------------- head: avg, pooled, classifier ----------------
__global__ void avg_kernel(const float* __restrict__ x, float* __restrict__ avg) {
    int b = blockIdx.x, hcol = threadIdx.x;
    float s = 0.0f;
    for (int ss = 0; ss < Ss; ss++) s += x[((size_t)(b*Ss + ss))*Hh + hcol];
    avg[b*Hh + hcol] = s * (1.0f/512.0f);
}

__global__ __launch_bounds__(128) void pool_kernel(
    const float* __restrict__ x, const float* __restrict__ pw,
    const float* __restrict__ pb, float* __restrict__ pool)
{
    int b = blockIdx.y;
    int o = blockIdx.x*128 + threadIdx.x;
    __shared__ float xb[768];
    for (int j = threadIdx.x; j < 768; j += 128) xb[j] = x[(size_t)(b*Ss)*Hh + j];
    __syncthreads();
    float s = 0.0f;
    for (int hcol = 0; hcol < 768; hcol++) s += xb[hcol]*pw[(size_t)hcol*Hh + o];
    pool[b*Hh + o] = tanhf(s + pb[o]);
}

__global__ void out_kernel(const float* __restrict__ avg, const float* __restrict__ pool,
                           const float* __restrict__ cw, const float* __restrict__ cb,
                           float* __restrict__ out)
{
    int b = blockIdx.x;
    int tid = threadIdx.x;
    int c = tid >> 5, lane = tid & 31;
    if (c >= NCc) return;
    float s = 0.0f;
    for (int t = lane; t < 2*Hh; t += 32) {
        float xv = (t < Hh) ? avg[b*Hh + t] : pool[b*Hh + t - Hh];
        s += xv * cw[(size_t)t*NCc + c];
    }
    for (int o = 16; o > 0; o >>= 1) s += __shfl_xor_sync(0xffffffff, s, o);
    if (lane == 0) out[b*NCc + c] = s + cb[c];
}

// ---------------- launch ----------------
extern "C" void kernel_launch(void* const* d_in, const int* in_sizes, int n_in,
                              void* d_out, int out_size)
{
    const int*   ids   = (const int*)  d_in[0];
    const int*   mask  = (const int*)  d_in[1];
    const float* we    = (const float*)d_in[2];
    const float* pe    = (const float*)d_in[3];
    const float* te    = (const float*)d_in[4];
    const float* lng   = (const float*)d_in[5];
    const float* lnb   = (const float*)d_in[6];
    const float* Wq    = (const float*)d_in[7];
    const float* bq    = (const float*)d_in[8];
    const float* Wk    = (const float*)d_in[9];
    const float* bk    = (const float*)d_in[10];
    const float* Wv    = (const float*)d_in[11];
    const float* bv    = (const float*)d_in[12];
    const float* Wo    = (const float*)d_in[13];
    const float* bo    = (const float*)d_in[14];
    const float* ln1g  = (const float*)d_in[15];
    const float* ln1b  = (const float*)d_in[16];
    const float* W1    = (const float*)d_in[17];
    const float* b1    = (const float*)d_in[18];
    const float* W2    = (const float*)d_in[19];
    const float* b2    = (const float*)d_in[20];
    const float* ln2g  = (const float*)d_in[21];
    const float* ln2b  = (const float*)d_in[22];
    const float* pw    = (const float*)d_in[23];
    const float* pb    = (const float*)d_in[24];
    const float* cw    = (const float*)d_in[25];
    const float* cb    = (const float*)d_in[26];
    float* out = (float*)d_out;

    float *x, *q, *k, *v, *ctx, *t, *ff, *tab, *avg, *pool, *S, *wbin;
    cudaGetSymbolAddress((void**)&x,    g_x);
    cudaGetSymbolAddress((void**)&q,    g_q);
    cudaGetSymbolAddress((void**)&k,    g_k);
    cudaGetSymbolAddress((void**)&v,    g_v);
    cudaGetSymbolAddress((void**)&ctx,  g_ctx);
    cudaGetSymbolAddress((void**)&t,    g_t);
    cudaGetSymbolAddress((void**)&ff,   g_ff);
    cudaGetSymbolAddress((void**)&tab,  g_tab);
    cudaGetSymbolAddress((void**)&avg,  g_avg);
    cudaGetSymbolAddress((void**)&pool, g_pool);
    cudaGetSymbolAddress((void**)&S,    g_S);
    cudaGetSymbolAddress((void**)&wbin, g_wbin);

    cudaFuncSetAttribute(attn_fused_kernel, cudaFuncAttributeMaxDynamicSharedMemorySize, FUSED_SMEM_BYTES);
    cudaFuncSetAttribute(attn_ctx_kernel,   cudaFuncAttributeMaxDynamicSharedMemorySize, CTX_SMEM_BYTES);

    tab_init_kernel<<<1, 256>>>(tab);
    embed_ln_kernel<<<MM, 256>>>(ids, we, pe, te, lng, lnb, x);

    dim3 gH(Hh/128, MM/128);     // (6, 32)
    dim3 gF(FFf/128, MM/128);    // (24, 32)
    dim3 gQKV(18, MM/128);
    dim3 gA(Ss/64, NHh, Bb);     // (8, 12, 8)

    for (int l = 0; l < Ll; l++) {
        tgemm_qkv_kernel<<<gQKV, 256>>>(x,
            Wq + (size_t)l*Hh*Hh, Wk + (size_t)l*Hh*Hh, Wv + (size_t)l*Hh*Hh,
            bq + l*Hh, bk + l*Hh, bv + l*Hh, q, k, v);
        attn_fused_kernel<<<gA, 256, FUSED_SMEM_BYTES>>>(q, k, tab, mask, S, wbin);
        attn_ctx_kernel<<<gA, 256, CTX_SMEM_BYTES>>>(S, v, wbin, tab, ctx);
        tgemm_kernel<<<gH, 256>>>(ctx, Wo + (size_t)l*Hh*Hh, bo + l*Hh, t, Hh, Hh, 0);
        add_ln_kernel<<<MM, 256>>>(x, t, ln1g + l*Hh, ln1b + l*Hh, x);
        tgemm_kernel<<<gF, 256>>>(x, W1 + (size_t)l*Hh*FFf, b1 + l*FFf, ff, FFf, Hh, 1);
        tgemm_kernel<<<gH, 256>>>(ff, W2 + (size_t)l*FFf*Hh, b2 + l*Hh, t, Hh, FFf, 0);
        add_ln_kernel<<<MM, 256>>>(x, t, ln2g + l*Hh, ln2b + l*Hh, x);
    }

    avg_kernel<<<Bb, Hh>>>(x, avg);
    pool_kernel<<<dim3(6, Bb), 128>>>(x, pw, pb, pool);
    out_kernel<<<Bb, 192>>>(avg, pool, cw, cb, out);
}